// round 12
// baseline (speedup 1.0000x reference)
#include <cuda_runtime.h>
#include <math.h>
#include <stdint.h>

#define Dm   1024
#define Hh   16
#define Bb   4
#define Ll   2048
#define MTOT (Bb * Ll)
#define NPLANE ((size_t)MTOT * Dm)
#define WPLANE ((size_t)Dm * Dm)
#define MB (1024ull * 1024ull)

// Scratch pool (no allocations): 160 MB
__device__ __align__(16) uint8_t g_buf[160 * MB];
// offsets: acts int8 q0,q1,k0,k1,v0,v1 @0 (6x8MB); W int8 @48MB (6x1MB);
// WO bf16 @54MB (2x2MB); Q/K int8 out @58MB (4x8MB); V bf16 @90MB (2x16MB);
// CTX bf16 @122MB (2x16MB)
#define OFF_ACT 0ull
#define OFF_W   (48ull*MB)
#define OFF_WO  (54ull*MB)
#define OFF_QK  (58ull*MB)
#define OFF_V   (90ull*MB)
#define OFF_CTX (122ull*MB)

__device__ __forceinline__ uint32_t smem_u32(const void* p) {
    uint32_t a;
    asm("{ .reg .u64 t; cvta.to.shared.u64 t, %1; cvt.u32.u64 %0, t; }"
        : "=r"(a) : "l"(p));
    return a;
}
__device__ __forceinline__ void split2(float x0, float x1,
                                       uint32_t& hi, uint32_t& lo) {
    uint32_t h;
    asm("cvt.rn.bf16x2.f32 %0, %1, %2;" : "=r"(h) : "f"(x1), "f"(x0));
    const float f0 = __uint_as_float(h << 16);
    const float f1 = __uint_as_float(h & 0xffff0000u);
    uint32_t l;
    asm("cvt.rn.bf16x2.f32 %0, %1, %2;" : "=r"(l) : "f"(x1 - f1), "f"(x0 - f0));
    hi = h; lo = l;
}
__device__ __forceinline__ void quant2(float f, int& q0, int& q1) {
    float fc = fminf(fmaxf(f, -127.f), 127.f);
    q0 = __float2int_rn(fc);
    float rr = (fc - (float)q0) * 256.f;
    q1 = __float2int_rn(fminf(fmaxf(rr, -127.f), 127.f));
}
__device__ __forceinline__ void mma_bf16(float d[4], const uint32_t a[4],
                                         const uint32_t b[2]) {
    asm volatile(
        "mma.sync.aligned.m16n8k16.row.col.f32.bf16.bf16.f32 "
        "{%0,%1,%2,%3}, {%4,%5,%6,%7}, {%8,%9}, {%0,%1,%2,%3};"
        : "+f"(d[0]), "+f"(d[1]), "+f"(d[2]), "+f"(d[3])
        : "r"(a[0]), "r"(a[1]), "r"(a[2]), "r"(a[3]), "r"(b[0]), "r"(b[1]));
}
__device__ __forceinline__ void mma_s8(int d[4], const uint32_t a[4],
                                       const uint32_t b[2]) {
    asm volatile(
        "mma.sync.aligned.m16n8k32.row.col.s32.s8.s8.s32 "
        "{%0,%1,%2,%3}, {%4,%5,%6,%7}, {%8,%9}, {%0,%1,%2,%3};"
        : "+r"(d[0]), "+r"(d[1]), "+r"(d[2]), "+r"(d[3])
        : "r"(a[0]), "r"(a[1]), "r"(a[2]), "r"(a[3]), "r"(b[0]), "r"(b[1]));
}
__device__ __forceinline__ void ldsm_x4(uint32_t r[4], uint32_t a) {
    asm volatile("ldmatrix.sync.aligned.m8n8.x4.shared.b16 {%0,%1,%2,%3}, [%4];"
                 : "=r"(r[0]), "=r"(r[1]), "=r"(r[2]), "=r"(r[3]) : "r"(a));
}
__device__ __forceinline__ void ldsm_x4_t(uint32_t r[4], uint32_t a) {
    asm volatile("ldmatrix.sync.aligned.m8n8.x4.trans.shared.b16 {%0,%1,%2,%3}, [%4];"
                 : "=r"(r[0]), "=r"(r[1]), "=r"(r[2]), "=r"(r[3]) : "r"(a));
}
#define CP16(smaddr, gptr) \
    asm volatile("cp.async.cg.shared.global [%0], [%1], 16;" \
                 :: "r"(smaddr), "l"(gptr))
#define CP_COMMIT() asm volatile("cp.async.commit_group;")

// fp32 -> int8 2-plane quantization, 3 tensors per launch
struct QuantB { const float* in[3]; uint8_t* p0[3]; uint8_t* p1[3]; float fs[3]; };
__global__ __launch_bounds__(256)
void quant_multi(QuantB qb, int n8)
{
    const int z = blockIdx.y;
    const float* in = qb.in[z];
    uint8_t* p0 = qb.p0[z];
    uint8_t* p1 = qb.p1[z];
    const float fs = qb.fs[z];
    const int i = blockIdx.x * 256 + threadIdx.x;
    if (i >= n8) return;
    const float4* in4 = (const float4*)in;
    float4 x = in4[2 * i], y = in4[2 * i + 1];
    float v[8] = {x.x, x.y, x.z, x.w, y.x, y.y, y.z, y.w};
    uint32_t a0 = 0, a1 = 0, b0 = 0, b1 = 0;
    #pragma unroll
    for (int j = 0; j < 4; j++) {
        int q0, q1;
        quant2(v[j] * fs, q0, q1);
        a0 |= (uint32_t)(q0 & 0xff) << (8 * j);
        a1 |= (uint32_t)(q1 & 0xff) << (8 * j);
        quant2(v[4 + j] * fs, q0, q1);
        b0 |= (uint32_t)(q0 & 0xff) << (8 * j);
        b1 |= (uint32_t)(q1 & 0xff) << (8 * j);
    }
    ((uint2*)p0)[i] = make_uint2(a0, b0);
    ((uint2*)p1)[i] = make_uint2(a1, b1);
}

// fp32 -> bf16 hi/lo split (wo only)
__global__ __launch_bounds__(256)
void split_one(const float* __restrict__ in, uint16_t* __restrict__ hi,
               uint16_t* __restrict__ lo, int n8)
{
    const int i = blockIdx.x * 256 + threadIdx.x;
    if (i >= n8) return;
    const float4* in4 = (const float4*)in;
    float4 x = in4[2 * i], y = in4[2 * i + 1];
    uint4 H, L;
    split2(x.x, x.y, H.x, L.x);
    split2(x.z, x.w, H.y, L.y);
    split2(y.x, y.y, H.z, L.z);
    split2(y.z, y.w, H.w, L.w);
    ((uint4*)hi)[i] = H;
    ((uint4*)lo)[i] = L;
}

// ---------------------------------------------------------------------------
// int8 2-plane GEMM: C = A@W^T + bias. CTA 128x64, 4 warps (2m x 2n, 64x32),
// KCH=32, 4-stage pipeline. Dequant: d0/8192 + dm/2097152 + d2/2^29.
// ---------------------------------------------------------------------------
#define IROWB 48
#define IAPL  (128 * IROWB)
#define IBPL  (64 * IROWB)
#define ISTAGE (2 * IAPL + 2 * IBPL)     // 18432
#define IGEMM_SMEM (4 * ISTAGE)          // 73728

struct S8Job {
    const uint8_t *A0, *A1, *B0, *B1;
    const float* bias;
    uint8_t *O0, *O1;    // int8 2-plane out (if outInt8)
    uint16_t *Ch, *Cl;   // bf16 planes out (if !outInt8)
    int outInt8;
};
struct S8Batch { S8Job j[3]; };

__global__ __launch_bounds__(128, 2)
void gemm_s8(S8Batch batch)
{
    extern __shared__ uint32_t smu[];
    const S8Job jb = batch.j[blockIdx.z];
    const int tid = threadIdx.x, warp = tid >> 5, lane = tid & 31;
    const int wm = warp & 1, wn = warp >> 1;
    const int m0 = blockIdx.y * 128, n0 = blockIdx.x * 64;
    const uint32_t smub = smem_u32(smu);
    const uint32_t aoff = (uint32_t)(((lane & 7) + ((lane >> 3) & 1) * 8) * IROWB +
                                     ((lane >> 4) << 4));
    const uint32_t boff = (uint32_t)(((lane & 7) + ((lane >> 4) << 3)) * IROWB +
                                     (((lane >> 3) & 1) << 4));

    int d0[4][4][4], dm[4][4][4], d2[4][4][4];
    #pragma unroll
    for (int mi = 0; mi < 4; mi++)
        #pragma unroll
        for (int nb = 0; nb < 4; nb++)
            #pragma unroll
            for (int x = 0; x < 4; x++) {
                d0[mi][nb][x] = 0; dm[mi][nb][x] = 0; d2[mi][nb][x] = 0;
            }

    auto fill = [&](int c) {
        const int k0 = c * 32;
        const uint32_t base = smub + (c & 3) * ISTAGE;
        #pragma unroll
        for (int i = 0; i < 6; i++) {
            const int f = tid + i * 128;
            if (f < 512) {
                const int pl = f >> 8, rr = (f & 255) >> 1, sg = f & 1;
                CP16(base + pl * IAPL + rr * IROWB + sg * 16,
                     (pl ? jb.A1 : jb.A0) + (size_t)(m0 + rr) * 1024 + k0 + sg * 16);
            } else {
                const int g = f - 512;
                const int pl = g >> 7, rr = (g & 127) >> 1, sg = g & 1;
                CP16(base + 2 * IAPL + pl * IBPL + rr * IROWB + sg * 16,
                     (pl ? jb.B1 : jb.B0) + (size_t)(n0 + rr) * 1024 + k0 + sg * 16);
            }
        }
        CP_COMMIT();
    };

    fill(0); fill(1); fill(2);

    for (int c = 0; c < 32; c++) {
        if (c) __syncthreads();
        if (c + 3 < 32) fill(c + 3);
        else CP_COMMIT();
        asm volatile("cp.async.wait_group 3;" ::: "memory");
        if (!c) __syncthreads();

        const uint32_t stB = smub + (c & 3) * ISTAGE;
        const uint32_t aA = stB + (uint32_t)(wm * 64 * IROWB) + aoff;
        const uint32_t aB = stB + 2 * IAPL + (uint32_t)(wn * 32 * IROWB) + boff;

        uint32_t a0[4][4], a1[4][4], b0[2][4], b1[2][4];
        #pragma unroll
        for (int mi = 0; mi < 4; mi++) ldsm_x4(a0[mi], aA + mi * 16 * IROWB);
        #pragma unroll
        for (int p = 0; p < 2; p++) ldsm_x4(b0[p], aB + p * 16 * IROWB);
        #pragma unroll
        for (int mi = 0; mi < 4; mi++)
            #pragma unroll
            for (int nb = 0; nb < 4; nb++)
                mma_s8(d0[mi][nb], a0[mi], &b0[nb >> 1][(nb & 1) * 2]);
        #pragma unroll
        for (int p = 0; p < 2; p++) ldsm_x4(b1[p], aB + IBPL + p * 16 * IROWB);
        #pragma unroll
        for (int mi = 0; mi < 4; mi++)
            #pragma unroll
            for (int nb = 0; nb < 4; nb++)
                mma_s8(dm[mi][nb], a0[mi], &b1[nb >> 1][(nb & 1) * 2]);
        #pragma unroll
        for (int mi = 0; mi < 4; mi++) ldsm_x4(a1[mi], aA + IAPL + mi * 16 * IROWB);
        #pragma unroll
        for (int mi = 0; mi < 4; mi++)
            #pragma unroll
            for (int nb = 0; nb < 4; nb++) {
                mma_s8(dm[mi][nb], a1[mi], &b0[nb >> 1][(nb & 1) * 2]);
                mma_s8(d2[mi][nb], a1[mi], &b1[nb >> 1][(nb & 1) * 2]);
            }
    }

    const float C1 = 1.220703125e-4f;        // 1/8192
    const float C2 = 4.76837158203125e-7f;   // 1/(8192*256)
    const float C3 = 1.86264514923096e-9f;   // 1/(8192*65536)
    const int row0 = m0 + wm * 64 + (lane >> 2);
    const int colb = n0 + wn * 32 + 2 * (lane & 3);
    #pragma unroll
    for (int nb = 0; nb < 4; nb++) {
        const int cc = colb + nb * 8;
        const float bb0 = jb.bias[cc], bb1 = jb.bias[cc + 1];
        #pragma unroll
        for (int mi = 0; mi < 4; mi++)
            #pragma unroll
            for (int hf = 0; hf < 2; hf++) {
                const int r = row0 + mi * 16 + 8 * hf;
                float v0 = fmaf((float)d2[mi][nb][2 * hf], C3,
                         fmaf((float)dm[mi][nb][2 * hf], C2,
                              (float)d0[mi][nb][2 * hf] * C1)) + bb0;
                float v1 = fmaf((float)d2[mi][nb][2 * hf + 1], C3,
                         fmaf((float)dm[mi][nb][2 * hf + 1], C2,
                              (float)d0[mi][nb][2 * hf + 1] * C1)) + bb1;
                if (jb.outInt8) {
                    int qa0, qa1, qb0, qb1;
                    quant2(v0 * 16.f, qa0, qa1);
                    quant2(v1 * 16.f, qb0, qb1);
                    const size_t idx = ((size_t)r * 1024 + cc) >> 1;
                    ((uint16_t*)jb.O0)[idx] =
                        (uint16_t)((qa0 & 0xff) | ((qb0 & 0xff) << 8));
                    ((uint16_t*)jb.O1)[idx] =
                        (uint16_t)((qa1 & 0xff) | ((qb1 & 0xff) << 8));
                } else {
                    uint32_t hv, lv;
                    split2(v0, v1, hv, lv);
                    ((uint32_t*)jb.Ch)[(size_t)r * 512 + cc / 2] = hv;
                    ((uint32_t*)jb.Cl)[(size_t)r * 512 + cc / 2] = lv;
                }
            }
    }
}

// ---------------------------------------------------------------------------
// split-bf16 GEMM (output projection): C = CTX @ Wo^T + bias -> fp32.
// ---------------------------------------------------------------------------
#define GROWB 48
#define GPLANEB (128 * GROWB)
#define GSTAGEB (4 * GPLANEB)
#define GEMM_SMEM_BYTES (4 * GSTAGEB)

__global__ __launch_bounds__(128, 2)
void gemm_bf16s(const uint16_t* __restrict__ Ah, const uint16_t* __restrict__ Al,
                const uint16_t* __restrict__ Bh, const uint16_t* __restrict__ Bl,
                const float* __restrict__ bias, float* __restrict__ Cf)
{
    extern __shared__ uint32_t smu[];
    const int tid = threadIdx.x, warp = tid >> 5, lane = tid & 31;
    const int wm = warp & 1, wn = warp >> 1;
    const int m0 = blockIdx.y * 128, n0 = blockIdx.x * 128;
    const uint32_t smub = smem_u32(smu);
    const uint32_t aoff = (uint32_t)(((lane & 7) + ((lane >> 3) & 1) * 8) * GROWB +
                                     ((lane >> 4) << 4));
    const uint32_t boff = (uint32_t)(((lane & 7) + ((lane >> 4) << 3)) * GROWB +
                                     (((lane >> 3) & 1) << 4));
    float d[4][8][4];
    #pragma unroll
    for (int mi = 0; mi < 4; mi++)
        #pragma unroll
        for (int ni = 0; ni < 8; ni++)
            #pragma unroll
            for (int x = 0; x < 4; x++) d[mi][ni][x] = 0.f;

    auto fill = [&](int c) {
        const int k0 = c * 16;
        const uint32_t base = smub + (c & 3) * GSTAGEB;
        const size_t ga = (size_t)(m0 + tid) * 1024 + k0;
        const size_t gb = (size_t)(n0 + tid) * 1024 + k0;
        const uint32_t so = (uint32_t)(tid * GROWB);
        #pragma unroll
        for (int sg = 0; sg < 2; sg++) {
            CP16(base + 0 * GPLANEB + so + sg * 16, Ah + ga + sg * 8);
            CP16(base + 1 * GPLANEB + so + sg * 16, Al + ga + sg * 8);
            CP16(base + 2 * GPLANEB + so + sg * 16, Bh + gb + sg * 8);
            CP16(base + 3 * GPLANEB + so + sg * 16, Bl + gb + sg * 8);
        }
        CP_COMMIT();
    };

    fill(0); fill(1); fill(2);
    for (int c = 0; c < 64; c++) {
        if (c) __syncthreads();
        if (c + 3 < 64) fill(c + 3);
        else CP_COMMIT();
        asm volatile("cp.async.wait_group 3;" ::: "memory");
        if (!c) __syncthreads();

        const uint32_t stB = smub + (c & 3) * GSTAGEB;
        const uint32_t aA = stB + (uint32_t)(wm * 64 * GROWB) + aoff;
        const uint32_t aB = stB + 2 * GPLANEB + (uint32_t)(wn * 64 * GROWB) + boff;

        uint32_t ah[4][4], bh[4][4], bl[4][4];
        #pragma unroll
        for (int mi = 0; mi < 4; mi++) ldsm_x4(ah[mi], aA + mi * 16 * GROWB);
        #pragma unroll
        for (int p = 0; p < 4; p++) ldsm_x4(bh[p], aB + p * 16 * GROWB);
        #pragma unroll
        for (int mi = 0; mi < 4; mi++)
            #pragma unroll
            for (int p = 0; p < 4; p++) {
                mma_bf16(d[mi][2 * p],     ah[mi], &bh[p][0]);
                mma_bf16(d[mi][2 * p + 1], ah[mi], &bh[p][2]);
            }
        #pragma unroll
        for (int p = 0; p < 4; p++) ldsm_x4(bl[p], aB + GPLANEB + p * 16 * GROWB);
        #pragma unroll
        for (int mi = 0; mi < 4; mi++)
            #pragma unroll
            for (int p = 0; p < 4; p++) {
                mma_bf16(d[mi][2 * p],     ah[mi], &bl[p][0]);
                mma_bf16(d[mi][2 * p + 1], ah[mi], &bl[p][2]);
            }
        #pragma unroll
        for (int mi = 0; mi < 4; mi++) ldsm_x4(ah[mi], aA + GPLANEB + mi * 16 * GROWB);
        #pragma unroll
        for (int mi = 0; mi < 4; mi++)
            #pragma unroll
            for (int p = 0; p < 4; p++) {
                mma_bf16(d[mi][2 * p],     ah[mi], &bh[p][0]);
                mma_bf16(d[mi][2 * p + 1], ah[mi], &bh[p][2]);
            }
    }

    const int row0 = m0 + wm * 64 + (lane >> 2);
    const int colb = n0 + wn * 64 + 2 * (lane & 3);
    #pragma unroll
    for (int ni = 0; ni < 8; ni++) {
        const int cc = colb + ni * 8;
        const float b0 = bias[cc], b1 = bias[cc + 1];
        #pragma unroll
        for (int mi = 0; mi < 4; mi++)
            #pragma unroll
            for (int hf = 0; hf < 2; hf++) {
                const int r = row0 + mi * 16 + 8 * hf;
                float2 w = {d[mi][ni][2 * hf] + b0, d[mi][ni][2 * hf + 1] + b1};
                *(float2*)(Cf + (size_t)r * 1024 + cc) = w;
            }
    }
}

// ---------------------------------------------------------------------------
// Flash attention (causal): QK^T int8 (2-plane, 4 products), PV split-bf16.
// Block = (b, h, 64-row q tile); 128 thr / 4 warps x 16 q-rows.
// ---------------------------------------------------------------------------
#define KROWB 80
#define KPL   (64 * KROWB)              // 5120
#define VROWB 144
#define VPL   (64 * VROWB)              // 9216
#define ASTAGEB (2 * KPL + 2 * VPL)     // 28672
#define ATT_SMEM (3 * ASTAGEB)          // 86016

__global__ __launch_bounds__(128, 2)
void attn_s8(const uint8_t* __restrict__ Qi0, const uint8_t* __restrict__ Qi1,
             const uint8_t* __restrict__ Ki0, const uint8_t* __restrict__ Ki1,
             const uint16_t* __restrict__ Vh, const uint16_t* __restrict__ Vl,
             uint16_t* __restrict__ Ch, uint16_t* __restrict__ Cl)
{
    extern __shared__ uint32_t smu[];
    const int tid = threadIdx.x, lane = tid & 31, warp = tid >> 5;
    const int r = lane >> 2, cth = lane & 3;
    const int qi = gridDim.x - 1 - blockIdx.x;
    const int hd = blockIdx.y, b = blockIdx.z;
    const int q0r = qi * 64;
    const uint32_t smub = smem_u32(smu);
    const size_t hoff = (size_t)hd * 64;

    const uint32_t koff = (uint32_t)(((lane & 7) + ((lane >> 4) << 3)) * KROWB +
                                     (((lane >> 3) & 1) << 4));
    const uint32_t aoffq = (uint32_t)(((lane & 7) + ((lane >> 3) & 1) * 8) * KROWB +
                                      ((lane >> 4) << 4));
    const uint32_t voff = (uint32_t)((lane & 15) * VROWB + ((lane >> 4) << 4));

    // Q int8 planes -> stage-2 area (group 0)
    #pragma unroll
    for (int i = 0; i < 4; i++) {
        const int f = tid + i * 128;
        const int pl = f >> 8, rr = (f & 255) >> 2, sg = f & 3;
        CP16(smub + 2 * ASTAGEB + pl * KPL + rr * KROWB + sg * 16,
             (pl ? Qi1 : Qi0) + (size_t)(b * Ll + q0r + rr) * 1024 + hoff + sg * 16);
    }
    CP_COMMIT();

    auto fillKV = [&](int kt) {
        const int k0 = kt * 64;
        const uint32_t dstB = smub + (kt % 3) * ASTAGEB;
        #pragma unroll
        for (int i = 0; i < 12; i++) {
            const int f = tid + i * 128;
            if (f < 512) {
                const int pl = f >> 8, rr = (f & 255) >> 2, sg = f & 3;
                CP16(dstB + pl * KPL + rr * KROWB + sg * 16,
                     (pl ? Ki1 : Ki0) + (size_t)(b * Ll + k0 + rr) * 1024 + hoff + sg * 16);
            } else {
                const int g = f - 512;
                const int pl = g >> 9, rr = (g & 511) >> 3, sg = g & 7;
                CP16(dstB + 2 * KPL + pl * VPL + rr * VROWB + sg * 16,
                     (pl ? Vl : Vh) + (size_t)(b * Ll + k0 + rr) * 1024 + hoff + sg * 8);
            }
        }
        CP_COMMIT();
    };

    fillKV(0);
    asm volatile("cp.async.wait_group 1;" ::: "memory");
    __syncthreads();

    uint32_t qa0[2][4], qa1[2][4];
    {
        const uint32_t qb = smub + 2 * ASTAGEB + (uint32_t)(warp * 16 * KROWB) + aoffq;
        #pragma unroll
        for (int j = 0; j < 2; j++) {
            ldsm_x4(qa0[j], qb + j * 32);
            ldsm_x4(qa1[j], qb + KPL + j * 32);
        }
    }
    __syncthreads();

    const int ktmax = qi + 1;
    if (ktmax > 1) fillKV(1);
    else CP_COMMIT();

    float m_i[2] = {-1e30f, -1e30f}, l_i[2] = {0.f, 0.f};
    float o[8][4];
    #pragma unroll
    for (int ni = 0; ni < 8; ni++)
        #pragma unroll
        for (int x = 0; x < 4; x++) o[ni][x] = 0.f;

    const float C1s = 4.8828125e-4f;         // 1/(16*16*8)
    const float C2s = 1.9073486328125e-6f;   // C1s/256
    const float C3s = 7.45058059692383e-9f;  // C1s/65536

    for (int kt = 0; kt < ktmax; kt++) {
        if (kt) __syncthreads();
        if (kt + 2 < ktmax) fillKV(kt + 2);
        else CP_COMMIT();
        asm volatile("cp.async.wait_group 2;" ::: "memory");
        if (!kt) __syncthreads();

        const uint32_t stB = smub + (kt % 3) * ASTAGEB;

        int d0[8][4], dmi[8][4], d2[8][4];
        #pragma unroll
        for (int ni = 0; ni < 8; ni++)
            #pragma unroll
            for (int x = 0; x < 4; x++) { d0[ni][x] = 0; dmi[ni][x] = 0; d2[ni][x] = 0; }

        #pragma unroll
        for (int j = 0; j < 2; j++) {
            #pragma unroll
            for (int nip = 0; nip < 4; nip++) {
                const uint32_t ka = stB + nip * (16 * KROWB) + koff + j * 32;
                uint32_t b0[4], b1[4];
                ldsm_x4(b0, ka);
                mma_s8(d0[2 * nip],      qa0[j], &b0[0]);
                mma_s8(d0[2 * nip + 1],  qa0[j], &b0[2]);
                mma_s8(dmi[2 * nip],     qa1[j], &b0[0]);
                mma_s8(dmi[2 * nip + 1], qa1[j], &b0[2]);
                ldsm_x4(b1, ka + KPL);
                mma_s8(dmi[2 * nip],     qa0[j], &b1[0]);
                mma_s8(dmi[2 * nip + 1], qa0[j], &b1[2]);
                mma_s8(d2[2 * nip],      qa1[j], &b1[0]);
                mma_s8(d2[2 * nip + 1],  qa1[j], &b1[2]);
            }
        }

        float sacc[8][4];
        #pragma unroll
        for (int ni = 0; ni < 8; ni++)
            #pragma unroll
            for (int x = 0; x < 4; x++)
                sacc[ni][x] = fmaf((float)d2[ni][x], C3s,
                              fmaf((float)dmi[ni][x], C2s,
                                   (float)d0[ni][x] * C1s));

        const int k0 = kt * 64;
        if (kt == ktmax - 1) {  // diagonal tile
            const int rowb = q0r + warp * 16 + r;
            #pragma unroll
            for (int ni = 0; ni < 8; ni++) {
                const int colb = k0 + ni * 8 + 2 * cth;
                #pragma unroll
                for (int x = 0; x < 4; x++)
                    if (colb + (x & 1) > rowb + 8 * (x >> 1)) sacc[ni][x] = -1e30f;
            }
        }

        #pragma unroll
        for (int h = 0; h < 2; h++) {
            float mx = -1e30f;
            #pragma unroll
            for (int ni = 0; ni < 8; ni++)
                mx = fmaxf(mx, fmaxf(sacc[ni][2 * h], sacc[ni][2 * h + 1]));
            mx = fmaxf(mx, __shfl_xor_sync(0xffffffffu, mx, 1));
            mx = fmaxf(mx, __shfl_xor_sync(0xffffffffu, mx, 2));
            const float mnew = fmaxf(m_i[h], mx);
            const float alpha = __expf(m_i[h] - mnew);
            float sum = 0.f;
            #pragma unroll
            for (int ni = 0; ni < 8; ni++) {
                const float p0 = __expf(sacc[ni][2 * h] - mnew);
                const float p1 = __expf(sacc[ni][2 * h + 1] - mnew);
                sum += p0 + p1;
                uint32_t hv, lv;
                split2(p0, p1, hv, lv);
                sacc[ni][2 * h]     = __uint_as_float(hv);
                sacc[ni][2 * h + 1] = __uint_as_float(lv);
                o[ni][2 * h]     *= alpha;
                o[ni][2 * h + 1] *= alpha;
            }
            sum += __shfl_xor_sync(0xffffffffu, sum, 1);
            sum += __shfl_xor_sync(0xffffffffu, sum, 2);
            l_i[h] = l_i[h] * alpha + sum;
            m_i[h] = mnew;
        }

        const uint32_t vB = stB + 2 * KPL;
        #pragma unroll
        for (int kk = 0; kk < 4; kk++) {
            uint32_t ph[4], pl[4];
            ph[0] = __float_as_uint(sacc[2 * kk][0]);
            ph[1] = __float_as_uint(sacc[2 * kk][2]);
            ph[2] = __float_as_uint(sacc[2 * kk + 1][0]);
            ph[3] = __float_as_uint(sacc[2 * kk + 1][2]);
            pl[0] = __float_as_uint(sacc[2 * kk][1]);
            pl[1] = __float_as_uint(sacc[2 * kk][3]);
            pl[2] = __float_as_uint(sacc[2 * kk + 1][1]);
            pl[3] = __float_as_uint(sacc[2 * kk + 1][3]);
            #pragma unroll
            for (int nip = 0; nip < 4; nip++) {
                const uint32_t va = vB + kk * (16 * VROWB) + nip * 32 + voff;
                uint32_t vh[4], vl[4];
                ldsm_x4_t(vh, va);
                mma_bf16(o[2 * nip],     ph, &vh[0]);
                mma_bf16(o[2 * nip + 1], ph, &vh[2]);
                mma_bf16(o[2 * nip],     pl, &vh[0]);
                mma_bf16(o[2 * nip + 1], pl, &vh[2]);
                ldsm_x4_t(vl, va + VPL);
                mma_bf16(o[2 * nip],     ph, &vl[0]);
                mma_bf16(o[2 * nip + 1], ph, &vl[2]);
            }
        }
    }

    #pragma unroll
    for (int h = 0; h < 2; h++) {
        const float inv = 1.0f / l_i[h];
        const int row = q0r + warp * 16 + r + 8 * h;
        const size_t base = ((size_t)(b * Ll + row)) * 512 + hd * 32;
        #pragma unroll
        for (int ni = 0; ni < 8; ni++) {
            uint32_t hv, lv;
            split2(o[ni][2 * h] * inv, o[ni][2 * h + 1] * inv, hv, lv);
            ((uint32_t*)Ch)[base + ni * 4 + cth] = hv;
            ((uint32_t*)Cl)[base + ni * 4 + cth] = lv;
        }
    }
}

// ---------------------------------------------------------------------------
extern "C" void kernel_launch(void* const* d_in, const int* in_sizes, int n_in,
                              void* d_out, int out_size)
{
    const float* q    = (const float*)d_in[0];
    const float* k    = (const float*)d_in[1];
    const float* v    = (const float*)d_in[2];
    const float* wq_w = (const float*)d_in[3];
    const float* wq_b = (const float*)d_in[4];
    const float* wk_w = (const float*)d_in[5];
    const float* wk_b = (const float*)d_in[6];
    const float* wv_w = (const float*)d_in[7];
    const float* wv_b = (const float*)d_in[8];
    const float* wo_w = (const float*)d_in[9];
    const float* wo_b = (const float*)d_in[10];
    float* out = (float*)d_out;

    uint8_t* B;
    cudaGetSymbolAddress((void**)&B, g_buf);
    uint8_t* act = B + OFF_ACT;                 // 6 planes x 8MB
    uint8_t* wgt = B + OFF_W;                   // 6 planes x 1MB
    uint16_t* woh = (uint16_t*)(B + OFF_WO);
    uint16_t* wol = woh + WPLANE;
    uint8_t* qk = B + OFF_QK;                   // Qi0,Qi1,Ki0,Ki1 x 8MB
    uint16_t* vh = (uint16_t*)(B + OFF_V);
    uint16_t* vl = vh + NPLANE;
    uint16_t* ch = (uint16_t*)(B + OFF_CTX);
    uint16_t* cl = ch + NPLANE;

    cudaFuncSetAttribute(gemm_s8, cudaFuncAttributeMaxDynamicSharedMemorySize,
                         IGEMM_SMEM);
    cudaFuncSetAttribute(gemm_bf16s, cudaFuncAttributeMaxDynamicSharedMemorySize,
                         GEMM_SMEM_BYTES);
    cudaFuncSetAttribute(attn_s8, cudaFuncAttributeMaxDynamicSharedMemorySize,
                         ATT_SMEM);

    const int n8a = (int)(NPLANE / 8), n8w = (int)(WPLANE / 8);

    QuantB qa;
    qa.in[0] = q; qa.p0[0] = act + 0 * NPLANE; qa.p1[0] = act + 1 * NPLANE; qa.fs[0] = 16.f;
    qa.in[1] = k; qa.p0[1] = act + 2 * NPLANE; qa.p1[1] = act + 3 * NPLANE; qa.fs[1] = 16.f;
    qa.in[2] = v; qa.p0[2] = act + 4 * NPLANE; qa.p1[2] = act + 5 * NPLANE; qa.fs[2] = 16.f;
    quant_multi<<<dim3(n8a / 256, 3), 256>>>(qa, n8a);

    QuantB qw;
    qw.in[0] = wq_w; qw.p0[0] = wgt + 0 * WPLANE; qw.p1[0] = wgt + 1 * WPLANE; qw.fs[0] = 512.f;
    qw.in[1] = wk_w; qw.p0[1] = wgt + 2 * WPLANE; qw.p1[1] = wgt + 3 * WPLANE; qw.fs[1] = 512.f;
    qw.in[2] = wv_w; qw.p0[2] = wgt + 4 * WPLANE; qw.p1[2] = wgt + 5 * WPLANE; qw.fs[2] = 512.f;
    quant_multi<<<dim3(n8w / 256, 3), 256>>>(qw, n8w);

    split_one<<<n8w / 256, 256>>>(wo_w, woh, wol, n8w);

    S8Batch proj;
    proj.j[0] = {act + 0 * NPLANE, act + 1 * NPLANE, wgt + 0 * WPLANE, wgt + 1 * WPLANE,
                 wq_b, qk + 0 * NPLANE, qk + 1 * NPLANE, nullptr, nullptr, 1};
    proj.j[1] = {act + 2 * NPLANE, act + 3 * NPLANE, wgt + 2 * WPLANE, wgt + 3 * WPLANE,
                 wk_b, qk + 2 * NPLANE, qk + 3 * NPLANE, nullptr, nullptr, 1};
    proj.j[2] = {act + 4 * NPLANE, act + 5 * NPLANE, wgt + 4 * WPLANE, wgt + 5 * WPLANE,
                 wv_b, nullptr, nullptr, vh, vl, 0};
    dim3 gg(1024 / 64, MTOT / 128, 3);   // (16, 64, 3)
    gemm_s8<<<gg, 128, IGEMM_SMEM>>>(proj);

    dim3 ga(Ll / 64, Hh, Bb);            // (32, 16, 4)
    attn_s8<<<ga, 128, ATT_SMEM>>>(qk + 0 * NPLANE, qk + 1 * NPLANE,
                                   qk + 2 * NPLANE, qk + 3 * NPLANE,
                                   vh, vl, ch, cl);

    dim3 go(1024 / 128, MTOT / 128);     // (8, 64)
    gemm_bf16s<<<go, 128, GEMM_SMEM_BYTES>>>(ch, cl, woh, wol, wo_b, out);
}

// round 13
// speedup vs baseline: 2.1536x; 2.1536x over previous
#include <cuda_runtime.h>
#include <cuda_fp16.h>
#include <math.h>
#include <stdint.h>

#define Dm   1024
#define Hh   16
#define Bb   4
#define Ll   2048
#define MTOT (Bb * Ll)
#define NPLANE ((size_t)MTOT * Dm)   // 8388608
#define WPLANE ((size_t)Dm * Dm)

// 240 MB fp16 scratch: planes 0-5 act splits (q,k,v hi/lo), 6-11 Q/K/V proj
// outputs (hi/lo), 12-13 ctx (hi/lo); then 8 weight planes (wq,wk,wv,wo hi/lo)
__device__ __align__(16) uint16_t g_buf[14 * NPLANE + 8 * WPLANE];

// lo planes are stored pre-scaled by 4096 (keeps them in fp16 normal range);
// cross-product sums are folded back with CFOLD = 2^-12.
#define CFOLD 2.44140625e-4f

__device__ __forceinline__ uint32_t smem_u32(const void* p) {
    uint32_t a;
    asm("{ .reg .u64 t; cvta.to.shared.u64 t, %1; cvt.u32.u64 %0, t; }"
        : "=r"(a) : "l"(p));
    return a;
}

// fp16 split: hi = rn(x), lo = (x - hi) * 4096
__device__ __forceinline__ void split2h(float x0, float x1,
                                        uint32_t& hi, uint32_t& lo) {
    __half2 hh = __floats2half2_rn(x0, x1);
    float2 fb = __half22float2(hh);
    __half2 ll = __floats2half2_rn((x0 - fb.x) * 4096.f, (x1 - fb.y) * 4096.f);
    hi = *(uint32_t*)&hh;
    lo = *(uint32_t*)&ll;
}

__device__ __forceinline__ float2 h2f2(uint32_t u) {
    return __half22float2(*(__half2*)&u);
}

// main product: fp32 accumulate
__device__ __forceinline__ void mma32(float d[4], const uint32_t a[4],
                                      const uint32_t b[2]) {
    asm volatile(
        "mma.sync.aligned.m16n8k16.row.col.f32.f16.f16.f32 "
        "{%0,%1,%2,%3}, {%4,%5,%6,%7}, {%8,%9}, {%0,%1,%2,%3};"
        : "+f"(d[0]), "+f"(d[1]), "+f"(d[2]), "+f"(d[3])
        : "r"(a[0]), "r"(a[1]), "r"(a[2]), "r"(a[3]), "r"(b[0]), "r"(b[1]));
}
// cross products: fp16 accumulate (2 packed regs)
__device__ __forceinline__ void mma16(uint32_t d[2], const uint32_t a[4],
                                      const uint32_t b[2]) {
    asm volatile(
        "mma.sync.aligned.m16n8k16.row.col.f16.f16.f16.f16 "
        "{%0,%1}, {%2,%3,%4,%5}, {%6,%7}, {%0,%1};"
        : "+r"(d[0]), "+r"(d[1])
        : "r"(a[0]), "r"(a[1]), "r"(a[2]), "r"(a[3]), "r"(b[0]), "r"(b[1]));
}

__device__ __forceinline__ void ldsm_x4(uint32_t r[4], uint32_t a) {
    asm volatile("ldmatrix.sync.aligned.m8n8.x4.shared.b16 {%0,%1,%2,%3}, [%4];"
                 : "=r"(r[0]), "=r"(r[1]), "=r"(r[2]), "=r"(r[3]) : "r"(a));
}
__device__ __forceinline__ void ldsm_x4_t(uint32_t r[4], uint32_t a) {
    asm volatile("ldmatrix.sync.aligned.m8n8.x4.trans.shared.b16 {%0,%1,%2,%3}, [%4];"
                 : "=r"(r[0]), "=r"(r[1]), "=r"(r[2]), "=r"(r[3]) : "r"(a));
}
#define CP16(smaddr, gptr) \
    asm volatile("cp.async.cg.shared.global [%0], [%1], 16;" \
                 :: "r"(smaddr), "l"(gptr))
#define CP_COMMIT() asm volatile("cp.async.commit_group;")

// ---------------------------------------------------------------------------
// fp32 -> fp16 hi/lo split, up to 4 tensors per launch
// ---------------------------------------------------------------------------
struct Split4 {
    const float* in[4];
    uint16_t* hi[4];
    uint16_t* lo[4];
};
__global__ __launch_bounds__(256)
void split_multi(Split4 a, int n8)
{
    const float* in = a.in[blockIdx.y];
    uint16_t* hi = a.hi[blockIdx.y];
    uint16_t* lo = a.lo[blockIdx.y];
    const int i = blockIdx.x * 256 + threadIdx.x;
    if (i >= n8) return;
    const float4* in4 = (const float4*)in;
    float4 x = in4[2 * i], y = in4[2 * i + 1];
    uint4 H, L;
    split2h(x.x, x.y, H.x, L.x);
    split2h(x.z, x.w, H.y, L.y);
    split2h(y.x, y.y, H.z, L.z);
    split2h(y.z, y.w, H.w, L.w);
    ((uint4*)hi)[i] = H;
    ((uint4*)lo)[i] = L;
}

// ---------------------------------------------------------------------------
// split-fp16 GEMM (batched over blockIdx.z): C = A @ W^T + bias.
// CTA 128x64, 4 warps (2m x 2n, warp 64x32), KCH=16, 4-stage pipeline.
// Main product fp32-acc; 2 cross products fp16-acc (lo planes x4096).
// ---------------------------------------------------------------------------
#define GROWB 48
#define GAPL  (128 * GROWB)        // 6144
#define GBPL  (64 * GROWB)         // 3072
#define GSTG  (2 * GAPL + 2 * GBPL)  // 18432
#define GEMM_SMEM (4 * GSTG)       // 73728

struct GemmJob {
    const uint16_t *Ah, *Al, *Bh, *Bl;
    const float* bias;
    float* Cf;           // fp32 out (or null)
    uint16_t *Ch, *Cl;   // fp16 plane out (if Cf null)
    float scale;
};
struct GemmBatch { GemmJob j[3]; };

__global__ __launch_bounds__(128, 2)
void gemm_f16s(GemmBatch batch)
{
    extern __shared__ uint32_t smu[];
    const GemmJob jb = batch.j[blockIdx.z];
    const int tid = threadIdx.x, warp = tid >> 5, lane = tid & 31;
    const int wm = warp & 1, wn = warp >> 1;
    const int m0 = blockIdx.y * 128, n0 = blockIdx.x * 64;
    const uint32_t smub = smem_u32(smu);
    const uint32_t aoff = (uint32_t)(((lane & 7) + ((lane >> 3) & 1) * 8) * GROWB +
                                     ((lane >> 4) << 4));
    const uint32_t boff = (uint32_t)(((lane & 7) + ((lane >> 4) << 3)) * GROWB +
                                     (((lane >> 3) & 1) << 4));

    float d[4][4][4];
    uint32_t dc[4][4][2];
    #pragma unroll
    for (int mi = 0; mi < 4; mi++)
        #pragma unroll
        for (int nb = 0; nb < 4; nb++) {
            #pragma unroll
            for (int x = 0; x < 4; x++) d[mi][nb][x] = 0.f;
            dc[mi][nb][0] = 0u; dc[mi][nb][1] = 0u;
        }

    auto fill = [&](int c) {
        const int k0 = c * 16;
        const uint32_t base = smub + (c & 3) * GSTG;
        #pragma unroll
        for (int i = 0; i < 6; i++) {
            const int f = tid + i * 128;
            if (f < 512) {
                const int pl = f >> 8, rr = (f & 255) >> 1, sg = f & 1;
                CP16(base + pl * GAPL + rr * GROWB + sg * 16,
                     (pl ? jb.Al : jb.Ah) + (size_t)(m0 + rr) * 1024 + k0 + sg * 8);
            } else {
                const int g = f - 512;
                const int pl = g >> 7, rr = (g & 127) >> 1, sg = g & 1;
                CP16(base + 2 * GAPL + pl * GBPL + rr * GROWB + sg * 16,
                     (pl ? jb.Bl : jb.Bh) + (size_t)(n0 + rr) * 1024 + k0 + sg * 8);
            }
        }
        CP_COMMIT();
    };

    fill(0); fill(1); fill(2);

    for (int c = 0; c < 64; c++) {
        if (c) __syncthreads();
        if (c + 3 < 64) fill(c + 3);
        else CP_COMMIT();
        asm volatile("cp.async.wait_group 3;" ::: "memory");
        if (!c) __syncthreads();

        const uint32_t stB = smub + (c & 3) * GSTG;
        const uint32_t aA = stB + (uint32_t)(wm * 64 * GROWB) + aoff;
        const uint32_t aB = stB + 2 * GAPL + (uint32_t)(wn * 32 * GROWB) + boff;

        uint32_t ah[4][4], al[4][4], bh[2][4], bl[2][4];
        #pragma unroll
        for (int mi = 0; mi < 4; mi++) ldsm_x4(ah[mi], aA + mi * 16 * GROWB);
        #pragma unroll
        for (int p = 0; p < 2; p++) ldsm_x4(bh[p], aB + p * 16 * GROWB);
        // main: Ah*Bh (fp32 acc)
        #pragma unroll
        for (int mi = 0; mi < 4; mi++)
            #pragma unroll
            for (int p = 0; p < 2; p++) {
                mma32(d[mi][2 * p],     ah[mi], &bh[p][0]);
                mma32(d[mi][2 * p + 1], ah[mi], &bh[p][2]);
            }
        // cross: Ah*Bl (fp16 acc)
        #pragma unroll
        for (int p = 0; p < 2; p++) ldsm_x4(bl[p], aB + GBPL + p * 16 * GROWB);
        #pragma unroll
        for (int mi = 0; mi < 4; mi++)
            #pragma unroll
            for (int p = 0; p < 2; p++) {
                mma16(dc[mi][2 * p],     ah[mi], &bl[p][0]);
                mma16(dc[mi][2 * p + 1], ah[mi], &bl[p][2]);
            }
        // cross: Al*Bh (fp16 acc)
        #pragma unroll
        for (int mi = 0; mi < 4; mi++) ldsm_x4(al[mi], aA + GAPL + mi * 16 * GROWB);
        #pragma unroll
        for (int mi = 0; mi < 4; mi++)
            #pragma unroll
            for (int p = 0; p < 2; p++) {
                mma16(dc[mi][2 * p],     al[mi], &bh[p][0]);
                mma16(dc[mi][2 * p + 1], al[mi], &bh[p][2]);
            }
    }

    const int row0 = m0 + wm * 64 + (lane >> 2);
    const int colb = n0 + wn * 32 + 2 * (lane & 3);
    #pragma unroll
    for (int nb = 0; nb < 4; nb++) {
        const int cc = colb + nb * 8;
        const float bb0 = jb.bias[cc], bb1 = jb.bias[cc + 1];
        #pragma unroll
        for (int mi = 0; mi < 4; mi++)
            #pragma unroll
            for (int hf = 0; hf < 2; hf++) {
                const int r = row0 + mi * 16 + 8 * hf;
                const float2 cr = h2f2(dc[mi][nb][hf]);
                float v0 = d[mi][nb][2 * hf]     + cr.x * CFOLD + bb0;
                float v1 = d[mi][nb][2 * hf + 1] + cr.y * CFOLD + bb1;
                if (jb.Cf) {
                    float2 w = {v0, v1};
                    *(float2*)(jb.Cf + (size_t)r * 1024 + cc) = w;
                } else {
                    uint32_t hv, lv;
                    split2h(v0 * jb.scale, v1 * jb.scale, hv, lv);
                    ((uint32_t*)jb.Ch)[(size_t)r * 512 + cc / 2] = hv;
                    ((uint32_t*)jb.Cl)[(size_t)r * 512 + cc / 2] = lv;
                }
            }
    }
}

// ---------------------------------------------------------------------------
// Flash attention (causal), split-fp16, cross products fp16-acc.
// Block = (b, h, 64-row q tile); 128 thr / 4 warps x 16 q-rows.
// 3-stage KV pipeline (Kh,Kl,Vh,Vl per stage); Q staged via stage-2 area.
// ---------------------------------------------------------------------------
#define KROWB 144
#define KPL   (64 * KROWB)            // 9216
#define ASTGB (4 * KPL)               // 36864
#define ATT_SMEM (3 * ASTGB)          // 110592

__global__ __launch_bounds__(128, 2)
void attn_f16s(const uint16_t* __restrict__ Qh, const uint16_t* __restrict__ Ql,
               const uint16_t* __restrict__ Kh, const uint16_t* __restrict__ Kl,
               const uint16_t* __restrict__ Vh, const uint16_t* __restrict__ Vl,
               uint16_t* __restrict__ Ch, uint16_t* __restrict__ Cl)
{
    extern __shared__ uint32_t smu[];
    const int tid = threadIdx.x, lane = tid & 31, warp = tid >> 5;
    const int r = lane >> 2, cth = lane & 3;
    const int qi = gridDim.x - 1 - blockIdx.x;   // heavy tiles first
    const int hd = blockIdx.y, b = blockIdx.z;
    const int q0r = qi * 64;
    const uint32_t smub = smem_u32(smu);
    const size_t hoff = (size_t)hd * 64;

    const uint32_t koff  = (uint32_t)(((lane & 7) + ((lane >> 4) << 3)) * KROWB +
                                      (((lane >> 3) & 1) << 4));
    const uint32_t aoffq = (uint32_t)(((lane & 7) + ((lane >> 3) & 1) * 8) * KROWB +
                                      ((lane >> 4) << 4));
    const uint32_t voff  = (uint32_t)((lane & 15) * KROWB + ((lane >> 4) << 4));

    // Q planes -> stage-2 area (group 0): 2 planes x 64 rows x 128 B
    #pragma unroll
    for (int i = 0; i < 8; i++) {
        const int f = tid + i * 128;       // 0..1023
        const int pl = f >> 9, rr = (f & 511) >> 3, sg = f & 7;
        CP16(smub + 2 * ASTGB + pl * KPL + rr * KROWB + sg * 16,
             (pl ? Ql : Qh) + (size_t)(b * Ll + q0r + rr) * 1024 + hoff + sg * 8);
    }
    CP_COMMIT();

    auto fillKV = [&](int kt) {
        const int k0 = kt * 64;
        const uint32_t dstB = smub + (kt % 3) * ASTGB;
        #pragma unroll
        for (int i = 0; i < 16; i++) {
            const int f = tid + i * 128;   // 0..2047
            const int pl = f >> 9, rr = (f & 511) >> 3, sg = f & 7;
            const uint16_t* src = (pl == 0 ? Kh : pl == 1 ? Kl : pl == 2 ? Vh : Vl);
            CP16(dstB + pl * KPL + rr * KROWB + sg * 16,
                 src + (size_t)(b * Ll + k0 + rr) * 1024 + hoff + sg * 8);
        }
        CP_COMMIT();
    };

    fillKV(0);
    asm volatile("cp.async.wait_group 1;" ::: "memory");   // Q ready
    __syncthreads();

    // preload Q fragments (hi + lo)
    uint32_t qh[4][4], ql[4][4];
    {
        const uint32_t qb = smub + 2 * ASTGB + (uint32_t)(warp * 16 * KROWB) + aoffq;
        #pragma unroll
        for (int j = 0; j < 4; j++) {
            ldsm_x4(qh[j], qb + j * 32);
            ldsm_x4(ql[j], qb + KPL + j * 32);
        }
    }
    __syncthreads();

    const int ktmax = qi + 1;
    if (ktmax > 1) fillKV(1);
    else CP_COMMIT();

    float m_i[2] = {-1e30f, -1e30f}, l_i[2] = {0.f, 0.f};
    float o[8][4];
    #pragma unroll
    for (int ni = 0; ni < 8; ni++)
        #pragma unroll
        for (int x = 0; x < 4; x++) o[ni][x] = 0.f;

    for (int kt = 0; kt < ktmax; kt++) {
        if (kt) __syncthreads();
        if (kt + 2 < ktmax) fillKV(kt + 2);
        else CP_COMMIT();
        asm volatile("cp.async.wait_group 2;" ::: "memory");
        if (!kt) __syncthreads();

        const uint32_t stB = smub + (kt % 3) * ASTGB;

        // S = (Q/8) K^T : main fp32-acc + cross fp16-acc
        float sacc[8][4];
        uint32_t sc[8][2];
        #pragma unroll
        for (int ni = 0; ni < 8; ni++) {
            #pragma unroll
            for (int x = 0; x < 4; x++) sacc[ni][x] = 0.f;
            sc[ni][0] = 0u; sc[ni][1] = 0u;
        }

        #pragma unroll
        for (int j = 0; j < 4; j++) {
            #pragma unroll
            for (int nip = 0; nip < 4; nip++) {
                const uint32_t ka = stB + nip * (16 * KROWB) + koff + j * 32;
                uint32_t bh[4], bl[4];
                ldsm_x4(bh, ka);
                mma32(sacc[2 * nip],     qh[j], &bh[0]);
                mma32(sacc[2 * nip + 1], qh[j], &bh[2]);
                mma16(sc[2 * nip],       ql[j], &bh[0]);
                mma16(sc[2 * nip + 1],   ql[j], &bh[2]);
                ldsm_x4(bl, ka + KPL);
                mma16(sc[2 * nip],       qh[j], &bl[0]);
                mma16(sc[2 * nip + 1],   qh[j], &bl[2]);
            }
        }
        #pragma unroll
        for (int ni = 0; ni < 8; ni++) {
            const float2 c0 = h2f2(sc[ni][0]);
            const float2 c1 = h2f2(sc[ni][1]);
            sacc[ni][0] += c0.x * CFOLD;
            sacc[ni][1] += c0.y * CFOLD;
            sacc[ni][2] += c1.x * CFOLD;
            sacc[ni][3] += c1.y * CFOLD;
        }

        const int k0 = kt * 64;
        if (kt == ktmax - 1) {  // diagonal tile
            const int rowb = q0r + warp * 16 + r;
            #pragma unroll
            for (int ni = 0; ni < 8; ni++) {
                const int colb = k0 + ni * 8 + 2 * cth;
                #pragma unroll
                for (int x = 0; x < 4; x++)
                    if (colb + (x & 1) > rowb + 8 * (x >> 1)) sacc[ni][x] = -1e30f;
            }
        }

        // online softmax; pack P as fp16 hi/lo (lo x4096) back into sacc bits
        #pragma unroll
        for (int h = 0; h < 2; h++) {
            float mx = -1e30f;
            #pragma unroll
            for (int ni = 0; ni < 8; ni++)
                mx = fmaxf(mx, fmaxf(sacc[ni][2 * h], sacc[ni][2 * h + 1]));
            mx = fmaxf(mx, __shfl_xor_sync(0xffffffffu, mx, 1));
            mx = fmaxf(mx, __shfl_xor_sync(0xffffffffu, mx, 2));
            const float mnew = fmaxf(m_i[h], mx);
            const float alpha = __expf(m_i[h] - mnew);
            float sum = 0.f;
            #pragma unroll
            for (int ni = 0; ni < 8; ni++) {
                const float p0 = __expf(sacc[ni][2 * h] - mnew);
                const float p1 = __expf(sacc[ni][2 * h + 1] - mnew);
                sum += p0 + p1;
                uint32_t hv, lv;
                split2h(p0, p1, hv, lv);
                sacc[ni][2 * h]     = __uint_as_float(hv);
                sacc[ni][2 * h + 1] = __uint_as_float(lv);
                o[ni][2 * h]     *= alpha;
                o[ni][2 * h + 1] *= alpha;
            }
            sum += __shfl_xor_sync(0xffffffffu, sum, 1);
            sum += __shfl_xor_sync(0xffffffffu, sum, 2);
            l_i[h] = l_i[h] * alpha + sum;
            m_i[h] = mnew;
        }

        // O += P V : main fp32-acc + cross fp16-acc (folded per iteration)
        const uint32_t vB = stB + 2 * KPL;
        uint32_t oc[8][2];
        #pragma unroll
        for (int ni = 0; ni < 8; ni++) { oc[ni][0] = 0u; oc[ni][1] = 0u; }

        #pragma unroll
        for (int kk = 0; kk < 4; kk++) {
            uint32_t ph[4], pl[4];
            ph[0] = __float_as_uint(sacc[2 * kk][0]);
            ph[1] = __float_as_uint(sacc[2 * kk][2]);
            ph[2] = __float_as_uint(sacc[2 * kk + 1][0]);
            ph[3] = __float_as_uint(sacc[2 * kk + 1][2]);
            pl[0] = __float_as_uint(sacc[2 * kk][1]);
            pl[1] = __float_as_uint(sacc[2 * kk][3]);
            pl[2] = __float_as_uint(sacc[2 * kk + 1][1]);
            pl[3] = __float_as_uint(sacc[2 * kk + 1][3]);
            #pragma unroll
            for (int nip = 0; nip < 4; nip++) {
                const uint32_t va = vB + kk * (16 * KROWB) + nip * 32 + voff;
                uint32_t vh4[4], vl4[4];
                ldsm_x4_t(vh4, va);
                mma32(o[2 * nip],      ph, &vh4[0]);
                mma32(o[2 * nip + 1],  ph, &vh4[2]);
                mma16(oc[2 * nip],     pl, &vh4[0]);
                mma16(oc[2 * nip + 1], pl, &vh4[2]);
                ldsm_x4_t(vl4, va + KPL);
                mma16(oc[2 * nip],     ph, &vl4[0]);
                mma16(oc[2 * nip + 1], ph, &vl4[2]);
            }
        }
        #pragma unroll
        for (int ni = 0; ni < 8; ni++) {
            const float2 c0 = h2f2(oc[ni][0]);
            const float2 c1 = h2f2(oc[ni][1]);
            o[ni][0] += c0.x * CFOLD;
            o[ni][1] += c0.y * CFOLD;
            o[ni][2] += c1.x * CFOLD;
            o[ni][3] += c1.y * CFOLD;
        }
    }

    // normalize + split + write context planes
    #pragma unroll
    for (int h = 0; h < 2; h++) {
        const float inv = 1.0f / l_i[h];
        const int row = q0r + warp * 16 + r + 8 * h;
        const size_t base = ((size_t)(b * Ll + row)) * 512 + hd * 32;
        #pragma unroll
        for (int ni = 0; ni < 8; ni++) {
            uint32_t hv, lv;
            split2h(o[ni][2 * h] * inv, o[ni][2 * h + 1] * inv, hv, lv);
            ((uint32_t*)Ch)[base + ni * 4 + cth] = hv;
            ((uint32_t*)Cl)[base + ni * 4 + cth] = lv;
        }
    }
}

// ---------------------------------------------------------------------------
extern "C" void kernel_launch(void* const* d_in, const int* in_sizes, int n_in,
                              void* d_out, int out_size)
{
    const float* q    = (const float*)d_in[0];
    const float* k    = (const float*)d_in[1];
    const float* v    = (const float*)d_in[2];
    const float* wq_w = (const float*)d_in[3];
    const float* wq_b = (const float*)d_in[4];
    const float* wk_w = (const float*)d_in[5];
    const float* wk_b = (const float*)d_in[6];
    const float* wv_w = (const float*)d_in[7];
    const float* wv_b = (const float*)d_in[8];
    const float* wo_w = (const float*)d_in[9];
    const float* wo_b = (const float*)d_in[10];
    float* out = (float*)d_out;

    uint16_t* P;
    cudaGetSymbolAddress((void**)&P, g_buf);
    uint16_t* W = P + 14 * NPLANE;
    #define PLN(i) (P + (size_t)(i) * NPLANE)
    #define WPL(i) (W + (size_t)(i) * WPLANE)

    cudaFuncSetAttribute(gemm_f16s, cudaFuncAttributeMaxDynamicSharedMemorySize,
                         GEMM_SMEM);
    cudaFuncSetAttribute(attn_f16s, cudaFuncAttributeMaxDynamicSharedMemorySize,
                         ATT_SMEM);

    const int n8a = (int)(NPLANE / 8), n8w = (int)(WPLANE / 8);

    Split4 sa;
    sa.in[0] = q; sa.hi[0] = PLN(0); sa.lo[0] = PLN(1);
    sa.in[1] = k; sa.hi[1] = PLN(2); sa.lo[1] = PLN(3);
    sa.in[2] = v; sa.hi[2] = PLN(4); sa.lo[2] = PLN(5);
    sa.in[3] = q; sa.hi[3] = PLN(0); sa.lo[3] = PLN(1);  // unused
    split_multi<<<dim3(n8a / 256, 3), 256>>>(sa, n8a);

    Split4 sw;
    sw.in[0] = wq_w; sw.hi[0] = WPL(0); sw.lo[0] = WPL(1);
    sw.in[1] = wk_w; sw.hi[1] = WPL(2); sw.lo[1] = WPL(3);
    sw.in[2] = wv_w; sw.hi[2] = WPL(4); sw.lo[2] = WPL(5);
    sw.in[3] = wo_w; sw.hi[3] = WPL(6); sw.lo[3] = WPL(7);
    split_multi<<<dim3(n8w / 256, 4), 256>>>(sw, n8w);

    // fused Q/K/V projections (Q pre-scaled by 1/8)
    GemmBatch proj;
    proj.j[0] = {PLN(0), PLN(1), WPL(0), WPL(1), wq_b, nullptr, PLN(6), PLN(7), 0.125f};
    proj.j[1] = {PLN(2), PLN(3), WPL(2), WPL(3), wk_b, nullptr, PLN(8), PLN(9), 1.0f};
    proj.j[2] = {PLN(4), PLN(5), WPL(4), WPL(5), wv_b, nullptr, PLN(10), PLN(11), 1.0f};
    dim3 gg(1024 / 64, MTOT / 128, 3);   // (16, 64, 3)
    gemm_f16s<<<gg, 128, GEMM_SMEM>>>(proj);

    dim3 ga(Ll / 64, Hh, Bb);            // (32, 16, 4)
    attn_f16s<<<ga, 128, ATT_SMEM>>>(PLN(6), PLN(7), PLN(8), PLN(9),
                                     PLN(10), PLN(11), PLN(12), PLN(13));

    // output projection -> fp32
    GemmBatch outp;
    outp.j[0] = {PLN(12), PLN(13), WPL(6), WPL(7), wo_b, out, nullptr, nullptr, 1.0f};
    outp.j[1] = outp.j[0];
    outp.j[2] = outp.j[0];
    dim3 go(1024 / 64, MTOT / 128, 1);   // (16, 64, 1)
    gemm_f16s<<<go, 128, GEMM_SMEM>>>(outp);
    #undef PLN
    #undef WPL
}

// round 14
// speedup vs baseline: 2.7508x; 1.2773x over previous
#include <cuda_runtime.h>
#include <cuda_fp16.h>
#include <math.h>
#include <stdint.h>

#define Dm   1024
#define Hh   16
#define Bb   4
#define Ll   2048
#define MTOT (Bb * Ll)
#define NPLANE ((size_t)MTOT * Dm)   // 8388608
#define WPLANE ((size_t)Dm * Dm)

// scratch: planes 0-5 act bf16 splits (q,k,v hi/lo); 6-8 Qf,Kf,Vf fp16;
// 9-10 ctx bf16 hi/lo; then 8 bf16 weight planes
__device__ __align__(16) uint16_t g_buf[11 * NPLANE + 8 * WPLANE];

__device__ __forceinline__ uint32_t smem_u32(const void* p) {
    uint32_t a;
    asm("{ .reg .u64 t; cvta.to.shared.u64 t, %1; cvt.u32.u64 %0, t; }"
        : "=r"(a) : "l"(p));
    return a;
}

// bf16 split (hi/lo) of two floats
__device__ __forceinline__ void split2(float x0, float x1,
                                       uint32_t& hi, uint32_t& lo) {
    uint32_t h;
    asm("cvt.rn.bf16x2.f32 %0, %1, %2;" : "=r"(h) : "f"(x1), "f"(x0));
    const float f0 = __uint_as_float(h << 16);
    const float f1 = __uint_as_float(h & 0xffff0000u);
    uint32_t l;
    asm("cvt.rn.bf16x2.f32 %0, %1, %2;" : "=r"(l) : "f"(x1 - f1), "f"(x0 - f0));
    hi = h; lo = l;
}
__device__ __forceinline__ uint32_t packh2(float x0, float x1) {
    __half2 h = __floats2half2_rn(x0, x1);
    return *(uint32_t*)&h;
}

// bf16 MMA, fp32 acc (projection path)
__device__ __forceinline__ void mma_bf16(float d[4], const uint32_t a[4],
                                         const uint32_t b[2]) {
    asm volatile(
        "mma.sync.aligned.m16n8k16.row.col.f32.bf16.bf16.f32 "
        "{%0,%1,%2,%3}, {%4,%5,%6,%7}, {%8,%9}, {%0,%1,%2,%3};"
        : "+f"(d[0]), "+f"(d[1]), "+f"(d[2]), "+f"(d[3])
        : "r"(a[0]), "r"(a[1]), "r"(a[2]), "r"(a[3]), "r"(b[0]), "r"(b[1]));
}
// fp16 MMA, fp32 acc (attention path)
__device__ __forceinline__ void mma_f16(float d[4], const uint32_t a[4],
                                        const uint32_t b[2]) {
    asm volatile(
        "mma.sync.aligned.m16n8k16.row.col.f32.f16.f16.f32 "
        "{%0,%1,%2,%3}, {%4,%5,%6,%7}, {%8,%9}, {%0,%1,%2,%3};"
        : "+f"(d[0]), "+f"(d[1]), "+f"(d[2]), "+f"(d[3])
        : "r"(a[0]), "r"(a[1]), "r"(a[2]), "r"(a[3]), "r"(b[0]), "r"(b[1]));
}
__device__ __forceinline__ void ldsm_x4(uint32_t r[4], uint32_t a) {
    asm volatile("ldmatrix.sync.aligned.m8n8.x4.shared.b16 {%0,%1,%2,%3}, [%4];"
                 : "=r"(r[0]), "=r"(r[1]), "=r"(r[2]), "=r"(r[3]) : "r"(a));
}
__device__ __forceinline__ void ldsm_x4_t(uint32_t r[4], uint32_t a) {
    asm volatile("ldmatrix.sync.aligned.m8n8.x4.trans.shared.b16 {%0,%1,%2,%3}, [%4];"
                 : "=r"(r[0]), "=r"(r[1]), "=r"(r[2]), "=r"(r[3]) : "r"(a));
}
#define CP16(smaddr, gptr) \
    asm volatile("cp.async.cg.shared.global [%0], [%1], 16;" \
                 :: "r"(smaddr), "l"(gptr))
#define CP_COMMIT() asm volatile("cp.async.commit_group;")

// ---------------------------------------------------------------------------
// fp32 -> bf16 hi/lo split, up to 4 tensors per launch
// ---------------------------------------------------------------------------
struct Split4 {
    const float* in[4];
    uint16_t* hi[4];
    uint16_t* lo[4];
};
__global__ __launch_bounds__(256)
void split_multi(Split4 a, int n8)
{
    const float* in = a.in[blockIdx.y];
    uint16_t* hi = a.hi[blockIdx.y];
    uint16_t* lo = a.lo[blockIdx.y];
    const int i = blockIdx.x * 256 + threadIdx.x;
    if (i >= n8) return;
    const float4* in4 = (const float4*)in;
    float4 x = in4[2 * i], y = in4[2 * i + 1];
    uint4 H, L;
    split2(x.x, x.y, H.x, L.x);
    split2(x.z, x.w, H.y, L.y);
    split2(y.x, y.y, H.z, L.z);
    split2(y.z, y.w, H.w, L.w);
    ((uint4*)hi)[i] = H;
    ((uint4*)lo)[i] = L;
}

// ---------------------------------------------------------------------------
// split-bf16 3-product GEMM (batched over z): C = A @ W^T + bias.
// CTA 128x128, 4 warps (2x2, warp 64x64), KCH=16, 4-stage pipeline.
// Output: fp32 (Cf) or single fp16 plane (Of, scaled).
// ---------------------------------------------------------------------------
#define GROWB 48
#define GPLANEB (128 * GROWB)
#define GSTAGEB (4 * GPLANEB)
#define GEMM_SMEM (4 * GSTAGEB)   // 98304

struct GemmJob {
    const uint16_t *Ah, *Al, *Bh, *Bl;
    const float* bias;
    float* Cf;          // fp32 out (or null)
    uint16_t* Of;       // fp16 out plane (if Cf null)
    float scale;
};
struct GemmBatch { GemmJob j[3]; };

__global__ __launch_bounds__(128, 2)
void gemm_bf16s(GemmBatch batch)
{
    extern __shared__ uint32_t smu[];
    const GemmJob jb = batch.j[blockIdx.z];
    const int tid = threadIdx.x, warp = tid >> 5, lane = tid & 31;
    const int wm = warp & 1, wn = warp >> 1;
    const int m0 = blockIdx.y * 128, n0 = blockIdx.x * 128;
    const uint32_t smub = smem_u32(smu);
    const uint32_t aoff = (uint32_t)(((lane & 7) + ((lane >> 3) & 1) * 8) * GROWB +
                                     ((lane >> 4) << 4));
    const uint32_t boff = (uint32_t)(((lane & 7) + ((lane >> 4) << 3)) * GROWB +
                                     (((lane >> 3) & 1) << 4));

    float d[4][8][4];
    #pragma unroll
    for (int mi = 0; mi < 4; mi++)
        #pragma unroll
        for (int ni = 0; ni < 8; ni++)
            #pragma unroll
            for (int x = 0; x < 4; x++) d[mi][ni][x] = 0.f;

    auto fill = [&](int c) {
        const int k0 = c * 16;
        const uint32_t base = smub + (c & 3) * GSTAGEB;
        const size_t ga = (size_t)(m0 + tid) * 1024 + k0;
        const size_t gb = (size_t)(n0 + tid) * 1024 + k0;
        const uint32_t so = (uint32_t)(tid * GROWB);
        #pragma unroll
        for (int sg = 0; sg < 2; sg++) {
            CP16(base + 0 * GPLANEB + so + sg * 16, jb.Ah + ga + sg * 8);
            CP16(base + 1 * GPLANEB + so + sg * 16, jb.Al + ga + sg * 8);
            CP16(base + 2 * GPLANEB + so + sg * 16, jb.Bh + gb + sg * 8);
            CP16(base + 3 * GPLANEB + so + sg * 16, jb.Bl + gb + sg * 8);
        }
        CP_COMMIT();
    };

    fill(0); fill(1); fill(2);

    for (int c = 0; c < 64; c++) {
        if (c) __syncthreads();
        if (c + 3 < 64) fill(c + 3);
        else CP_COMMIT();
        asm volatile("cp.async.wait_group 3;" ::: "memory");
        if (!c) __syncthreads();

        const uint32_t stB = smub + (c & 3) * GSTAGEB;
        const uint32_t aA = stB + (uint32_t)(wm * 64 * GROWB) + aoff;
        const uint32_t aB = stB + 2 * GPLANEB + (uint32_t)(wn * 64 * GROWB) + boff;

        uint32_t ah[4][4], bh[4][4], bl[4][4];
        #pragma unroll
        for (int mi = 0; mi < 4; mi++) ldsm_x4(ah[mi], aA + mi * 16 * GROWB);
        #pragma unroll
        for (int p = 0; p < 4; p++) ldsm_x4(bh[p], aB + p * 16 * GROWB);
        #pragma unroll
        for (int mi = 0; mi < 4; mi++)
            #pragma unroll
            for (int p = 0; p < 4; p++) {
                mma_bf16(d[mi][2 * p],     ah[mi], &bh[p][0]);
                mma_bf16(d[mi][2 * p + 1], ah[mi], &bh[p][2]);
            }
        #pragma unroll
        for (int p = 0; p < 4; p++) ldsm_x4(bl[p], aB + GPLANEB + p * 16 * GROWB);
        #pragma unroll
        for (int mi = 0; mi < 4; mi++)
            #pragma unroll
            for (int p = 0; p < 4; p++) {
                mma_bf16(d[mi][2 * p],     ah[mi], &bl[p][0]);
                mma_bf16(d[mi][2 * p + 1], ah[mi], &bl[p][2]);
            }
        #pragma unroll
        for (int mi = 0; mi < 4; mi++) ldsm_x4(ah[mi], aA + GPLANEB + mi * 16 * GROWB);
        #pragma unroll
        for (int mi = 0; mi < 4; mi++)
            #pragma unroll
            for (int p = 0; p < 4; p++) {
                mma_bf16(d[mi][2 * p],     ah[mi], &bh[p][0]);
                mma_bf16(d[mi][2 * p + 1], ah[mi], &bh[p][2]);
            }
    }

    const int row0 = m0 + wm * 64 + (lane >> 2);
    const int colb = n0 + wn * 64 + 2 * (lane & 3);
    #pragma unroll
    for (int ni = 0; ni < 8; ni++) {
        const int cc = colb + ni * 8;
        const float b0 = jb.bias[cc], b1 = jb.bias[cc + 1];
        #pragma unroll
        for (int mi = 0; mi < 4; mi++)
            #pragma unroll
            for (int hf = 0; hf < 2; hf++) {
                const int r = row0 + mi * 16 + 8 * hf;
                const float v0 = d[mi][ni][2 * hf]     + b0;
                const float v1 = d[mi][ni][2 * hf + 1] + b1;
                if (jb.Cf) {
                    float2 w = {v0, v1};
                    *(float2*)(jb.Cf + (size_t)r * 1024 + cc) = w;
                } else {
                    ((uint32_t*)jb.Of)[(size_t)r * 512 + cc / 2] =
                        packh2(v0 * jb.scale, v1 * jb.scale);
                }
            }
    }
}

// ---------------------------------------------------------------------------
// Flash attention (causal), fp16 SINGLE-product MMAs (fp32 acc).
// Block = (b, h, 64-row q tile); 128 thr / 4 warps x 16 q-rows; 64-key iters.
// 3-stage KV pipeline (K,V single fp16 planes); Q staged via stage-2 area.
// ---------------------------------------------------------------------------
#define KROWB 144
#define KPL   (64 * KROWB)          // 9216 B
#define ASTGB (2 * KPL)             // 18432 B
#define ATT_SMEM (3 * ASTGB)        // 55296 B

__global__ __launch_bounds__(128, 2)
void attn_f16(const uint16_t* __restrict__ Qf, const uint16_t* __restrict__ Kf,
              const uint16_t* __restrict__ Vf,
              uint16_t* __restrict__ Ch, uint16_t* __restrict__ Cl)
{
    extern __shared__ uint32_t smu[];
    const int tid = threadIdx.x, lane = tid & 31, warp = tid >> 5;
    const int r = lane >> 2, cth = lane & 3;
    const int qi = gridDim.x - 1 - blockIdx.x;   // heavy tiles first
    const int hd = blockIdx.y, b = blockIdx.z;
    const int q0r = qi * 64;
    const uint32_t smub = smem_u32(smu);
    const size_t hoff = (size_t)hd * 64;

    const uint32_t koff  = (uint32_t)(((lane & 7) + ((lane >> 4) << 3)) * KROWB +
                                      (((lane >> 3) & 1) << 4));
    const uint32_t aoffq = (uint32_t)(((lane & 7) + ((lane >> 3) & 1) * 8) * KROWB +
                                      ((lane >> 4) << 4));
    const uint32_t voff  = (uint32_t)((lane & 15) * KROWB + ((lane >> 4) << 4));

    // Q plane -> stage-2 area (group 0): 64 rows x 128 B
    #pragma unroll
    for (int i = 0; i < 4; i++) {
        const int f = tid + i * 128;       // 0..511
        const int rr = f >> 3, sg = f & 7;
        CP16(smub + 2 * ASTGB + rr * KROWB + sg * 16,
             Qf + (size_t)(b * Ll + q0r + rr) * 1024 + hoff + sg * 8);
    }
    CP_COMMIT();

    auto fillKV = [&](int kt) {
        const int k0 = kt * 64;
        const uint32_t dstB = smub + (kt % 3) * ASTGB;
        #pragma unroll
        for (int i = 0; i < 8; i++) {
            const int f = tid + i * 128;   // 0..1023
            const int pl = f >> 9, rr = (f & 511) >> 3, sg = f & 7;
            const uint16_t* src = pl ? Vf : Kf;
            CP16(dstB + pl * KPL + rr * KROWB + sg * 16,
                 src + (size_t)(b * Ll + k0 + rr) * 1024 + hoff + sg * 8);
        }
        CP_COMMIT();
    };

    fillKV(0);
    asm volatile("cp.async.wait_group 1;" ::: "memory");   // Q ready
    __syncthreads();

    // preload Q fragments (already scaled 1/8 at projection)
    uint32_t qf[4][4];
    {
        const uint32_t qb = smub + 2 * ASTGB + (uint32_t)(warp * 16 * KROWB) + aoffq;
        #pragma unroll
        for (int j = 0; j < 4; j++) ldsm_x4(qf[j], qb + j * 32);
    }
    __syncthreads();

    const int ktmax = qi + 1;
    if (ktmax > 1) fillKV(1);
    else CP_COMMIT();

    float m_i[2] = {-1e30f, -1e30f}, l_i[2] = {0.f, 0.f};
    float o[8][4];
    #pragma unroll
    for (int ni = 0; ni < 8; ni++)
        #pragma unroll
        for (int x = 0; x < 4; x++) o[ni][x] = 0.f;

    for (int kt = 0; kt < ktmax; kt++) {
        if (kt) __syncthreads();
        if (kt + 2 < ktmax) fillKV(kt + 2);
        else CP_COMMIT();
        asm volatile("cp.async.wait_group 2;" ::: "memory");
        if (!kt) __syncthreads();

        const uint32_t stB = smub + (kt % 3) * ASTGB;

        // S = (Q/8) K^T  (single product)
        float sacc[8][4];
        #pragma unroll
        for (int ni = 0; ni < 8; ni++)
            #pragma unroll
            for (int x = 0; x < 4; x++) sacc[ni][x] = 0.f;

        #pragma unroll
        for (int j = 0; j < 4; j++) {
            #pragma unroll
            for (int nip = 0; nip < 4; nip++) {
                const uint32_t ka = stB + nip * (16 * KROWB) + koff + j * 32;
                uint32_t bf[4];
                ldsm_x4(bf, ka);
                mma_f16(sacc[2 * nip],     qf[j], &bf[0]);
                mma_f16(sacc[2 * nip + 1], qf[j], &bf[2]);
            }
        }

        const int k0 = kt * 64;
        if (kt == ktmax - 1) {  // diagonal tile
            const int rowb = q0r + warp * 16 + r;
            #pragma unroll
            for (int ni = 0; ni < 8; ni++) {
                const int colb = k0 + ni * 8 + 2 * cth;
                #pragma unroll
                for (int x = 0; x < 4; x++)
                    if (colb + (x & 1) > rowb + 8 * (x >> 1)) sacc[ni][x] = -1e30f;
            }
        }

        // online softmax; P packed fp16 pairs (row, row+8 halves)
        uint32_t pp[8][2];
        #pragma unroll
        for (int h = 0; h < 2; h++) {
            float mx = -1e30f;
            #pragma unroll
            for (int ni = 0; ni < 8; ni++)
                mx = fmaxf(mx, fmaxf(sacc[ni][2 * h], sacc[ni][2 * h + 1]));
            mx = fmaxf(mx, __shfl_xor_sync(0xffffffffu, mx, 1));
            mx = fmaxf(mx, __shfl_xor_sync(0xffffffffu, mx, 2));
            const float mnew = fmaxf(m_i[h], mx);
            const float alpha = __expf(m_i[h] - mnew);
            float sum = 0.f;
            #pragma unroll
            for (int ni = 0; ni < 8; ni++) {
                const float p0 = __expf(sacc[ni][2 * h] - mnew);
                const float p1 = __expf(sacc[ni][2 * h + 1] - mnew);
                sum += p0 + p1;
                pp[ni][h] = packh2(p0, p1);
                o[ni][2 * h]     *= alpha;
                o[ni][2 * h + 1] *= alpha;
            }
            sum += __shfl_xor_sync(0xffffffffu, sum, 1);
            sum += __shfl_xor_sync(0xffffffffu, sum, 2);
            l_i[h] = l_i[h] * alpha + sum;
            m_i[h] = mnew;
        }

        // O += P V (single product; P A-frags from registers, V via ldsm.trans)
        const uint32_t vB = stB + KPL;
        #pragma unroll
        for (int kk = 0; kk < 4; kk++) {
            uint32_t ah[4];
            ah[0] = pp[2 * kk][0];
            ah[1] = pp[2 * kk][1];
            ah[2] = pp[2 * kk + 1][0];
            ah[3] = pp[2 * kk + 1][1];
            #pragma unroll
            for (int nip = 0; nip < 4; nip++) {
                const uint32_t va = vB + kk * (16 * KROWB) + nip * 32 + voff;
                uint32_t vf4[4];
                ldsm_x4_t(vf4, va);
                mma_f16(o[2 * nip],     ah, &vf4[0]);
                mma_f16(o[2 * nip + 1], ah, &vf4[2]);
            }
        }
    }

    // normalize + bf16-split + write context planes
    #pragma unroll
    for (int h = 0; h < 2; h++) {
        const float inv = 1.0f / l_i[h];
        const int row = q0r + warp * 16 + r + 8 * h;
        const size_t base = ((size_t)(b * Ll + row)) * 512 + hd * 32;
        #pragma unroll
        for (int ni = 0; ni < 8; ni++) {
            uint32_t hv, lv;
            split2(o[ni][2 * h] * inv, o[ni][2 * h + 1] * inv, hv, lv);
            ((uint32_t*)Ch)[base + ni * 4 + cth] = hv;
            ((uint32_t*)Cl)[base + ni * 4 + cth] = lv;
        }
    }
}

// ---------------------------------------------------------------------------
extern "C" void kernel_launch(void* const* d_in, const int* in_sizes, int n_in,
                              void* d_out, int out_size)
{
    const float* q    = (const float*)d_in[0];
    const float* k    = (const float*)d_in[1];
    const float* v    = (const float*)d_in[2];
    const float* wq_w = (const float*)d_in[3];
    const float* wq_b = (const float*)d_in[4];
    const float* wk_w = (const float*)d_in[5];
    const float* wk_b = (const float*)d_in[6];
    const float* wv_w = (const float*)d_in[7];
    const float* wv_b = (const float*)d_in[8];
    const float* wo_w = (const float*)d_in[9];
    const float* wo_b = (const float*)d_in[10];
    float* out = (float*)d_out;

    uint16_t* P;
    cudaGetSymbolAddress((void**)&P, g_buf);
    uint16_t* W = P + 11 * NPLANE;
    #define PLN(i) (P + (size_t)(i) * NPLANE)
    #define WPL(i) (W + (size_t)(i) * WPLANE)

    cudaFuncSetAttribute(gemm_bf16s, cudaFuncAttributeMaxDynamicSharedMemorySize,
                         GEMM_SMEM);
    cudaFuncSetAttribute(attn_f16, cudaFuncAttributeMaxDynamicSharedMemorySize,
                         ATT_SMEM);

    const int n8a = (int)(NPLANE / 8), n8w = (int)(WPLANE / 8);

    Split4 sa;
    sa.in[0] = q; sa.hi[0] = PLN(0); sa.lo[0] = PLN(1);
    sa.in[1] = k; sa.hi[1] = PLN(2); sa.lo[1] = PLN(3);
    sa.in[2] = v; sa.hi[2] = PLN(4); sa.lo[2] = PLN(5);
    sa.in[3] = q; sa.hi[3] = PLN(0); sa.lo[3] = PLN(1);  // unused
    split_multi<<<dim3(n8a / 256, 3), 256>>>(sa, n8a);

    Split4 sw;
    sw.in[0] = wq_w; sw.hi[0] = WPL(0); sw.lo[0] = WPL(1);
    sw.in[1] = wk_w; sw.hi[1] = WPL(2); sw.lo[1] = WPL(3);
    sw.in[2] = wv_w; sw.hi[2] = WPL(4); sw.lo[2] = WPL(5);
    sw.in[3] = wo_w; sw.hi[3] = WPL(6); sw.lo[3] = WPL(7);
    split_multi<<<dim3(n8w / 256, 4), 256>>>(sw, n8w);

    // fused Q/K/V projections -> fp16 planes (Q pre-scaled by 1/8)
    GemmBatch proj;
    proj.j[0] = {PLN(0), PLN(1), WPL(0), WPL(1), wq_b, nullptr, PLN(6), 0.125f};
    proj.j[1] = {PLN(2), PLN(3), WPL(2), WPL(3), wk_b, nullptr, PLN(7), 1.0f};
    proj.j[2] = {PLN(4), PLN(5), WPL(4), WPL(5), wv_b, nullptr, PLN(8), 1.0f};
    dim3 gg(1024 / 128, MTOT / 128, 3);   // (8, 64, 3)
    gemm_bf16s<<<gg, 128, GEMM_SMEM>>>(proj);

    dim3 ga(Ll / 64, Hh, Bb);             // (32, 16, 4)
    attn_f16<<<ga, 128, ATT_SMEM>>>(PLN(6), PLN(7), PLN(8), PLN(9), PLN(10));

    // output projection (bf16-3) -> fp32
    GemmBatch outp;
    outp.j[0] = {PLN(9), PLN(10), WPL(6), WPL(7), wo_b, out, nullptr, 1.0f};
    outp.j[1] = outp.j[0];
    outp.j[2] = outp.j[0];
    dim3 go(1024 / 128, MTOT / 128, 1);   // (8, 64, 1)
    gemm_bf16s<<<go, 128, GEMM_SMEM>>>(outp);
    #undef PLN
    #undef WPL
}

// round 16
// speedup vs baseline: 3.5303x; 1.2833x over previous
#include <cuda_runtime.h>
#include <cuda_fp16.h>
#include <math.h>
#include <stdint.h>

#define Dm   1024
#define Hh   16
#define Bb   4
#define Ll   2048
#define MTOT (Bb * Ll)
#define NPLANE ((size_t)MTOT * Dm)   // 8388608
#define WPLANE ((size_t)Dm * Dm)

// planes 0-5: act fp16 hi/lo (q,k,v); 6-8: Qf,Kf,Vf fp16; 9-10: ctx bf16 hi/lo
// weights: wq,wk,wv single fp16 (WPL 0-2); wo bf16 hi/lo (WPL 3-4)
__device__ __align__(16) uint16_t g_buf[11 * NPLANE + 5 * WPLANE];

__device__ __forceinline__ uint32_t smem_u32(const void* p) {
    uint32_t a;
    asm("{ .reg .u64 t; cvta.to.shared.u64 t, %1; cvt.u32.u64 %0, t; }"
        : "=r"(a) : "l"(p));
    return a;
}

// bf16 split (hi/lo)
__device__ __forceinline__ void split2(float x0, float x1,
                                       uint32_t& hi, uint32_t& lo) {
    uint32_t h;
    asm("cvt.rn.bf16x2.f32 %0, %1, %2;" : "=r"(h) : "f"(x1), "f"(x0));
    const float f0 = __uint_as_float(h << 16);
    const float f1 = __uint_as_float(h & 0xffff0000u);
    uint32_t l;
    asm("cvt.rn.bf16x2.f32 %0, %1, %2;" : "=r"(l) : "f"(x1 - f1), "f"(x0 - f0));
    hi = h; lo = l;
}
// fp16 split (hi/lo, unscaled lo)
__device__ __forceinline__ void split2h(float x0, float x1,
                                        uint32_t& hi, uint32_t& lo) {
    __half2 hh = __floats2half2_rn(x0, x1);
    float2 fb = __half22float2(hh);
    __half2 ll = __floats2half2_rn(x0 - fb.x, x1 - fb.y);
    hi = *(uint32_t*)&hh;
    lo = *(uint32_t*)&ll;
}
__device__ __forceinline__ uint32_t packh2(float x0, float x1) {
    __half2 h = __floats2half2_rn(x0, x1);
    return *(uint32_t*)&h;
}

__device__ __forceinline__ void mma_bf16(float d[4], const uint32_t a[4],
                                         const uint32_t b[2]) {
    asm volatile(
        "mma.sync.aligned.m16n8k16.row.col.f32.bf16.bf16.f32 "
        "{%0,%1,%2,%3}, {%4,%5,%6,%7}, {%8,%9}, {%0,%1,%2,%3};"
        : "+f"(d[0]), "+f"(d[1]), "+f"(d[2]), "+f"(d[3])
        : "r"(a[0]), "r"(a[1]), "r"(a[2]), "r"(a[3]), "r"(b[0]), "r"(b[1]));
}
__device__ __forceinline__ void mma_f16(float d[4], const uint32_t a[4],
                                        const uint32_t b[2]) {
    asm volatile(
        "mma.sync.aligned.m16n8k16.row.col.f32.f16.f16.f32 "
        "{%0,%1,%2,%3}, {%4,%5,%6,%7}, {%8,%9}, {%0,%1,%2,%3};"
        : "+f"(d[0]), "+f"(d[1]), "+f"(d[2]), "+f"(d[3])
        : "r"(a[0]), "r"(a[1]), "r"(a[2]), "r"(a[3]), "r"(b[0]), "r"(b[1]));
}
__device__ __forceinline__ void ldsm_x4(uint32_t r[4], uint32_t a) {
    asm volatile("ldmatrix.sync.aligned.m8n8.x4.shared.b16 {%0,%1,%2,%3}, [%4];"
                 : "=r"(r[0]), "=r"(r[1]), "=r"(r[2]), "=r"(r[3]) : "r"(a));
}
__device__ __forceinline__ void ldsm_x4_t(uint32_t r[4], uint32_t a) {
    asm volatile("ldmatrix.sync.aligned.m8n8.x4.trans.shared.b16 {%0,%1,%2,%3}, [%4];"
                 : "=r"(r[0]), "=r"(r[1]), "=r"(r[2]), "=r"(r[3]) : "r"(a));
}
#define CP16(smaddr, gptr) \
    asm volatile("cp.async.cg.shared.global [%0], [%1], 16;" \
                 :: "r"(smaddr), "l"(gptr))
#define CP_COMMIT() asm volatile("cp.async.commit_group;")

// ---------------------------------------------------------------------------
// Split kernels. lo != null -> hi/lo split; lo == null -> single fp16 plane.
// ---------------------------------------------------------------------------
struct Split4 {
    const float* in[4];
    uint16_t* hi[4];
    uint16_t* lo[4];
    int bf16[4];
};
__global__ __launch_bounds__(256)
void split_multi(Split4 a, int n8)
{
    const int z = blockIdx.y;
    const float* in = a.in[z];
    uint16_t* hi = a.hi[z];
    uint16_t* lo = a.lo[z];
    const int isbf = a.bf16[z];
    const int i = blockIdx.x * 256 + threadIdx.x;
    if (i >= n8) return;
    const float4* in4 = (const float4*)in;
    float4 x = in4[2 * i], y = in4[2 * i + 1];
    float v[8] = {x.x, x.y, x.z, x.w, y.x, y.y, y.z, y.w};
    uint4 H, L;
    uint32_t* Hp = &H.x;
    uint32_t* Lp = &L.x;
    #pragma unroll
    for (int j = 0; j < 4; j++) {
        if (lo) {
            if (isbf) split2(v[2 * j], v[2 * j + 1], Hp[j], Lp[j]);
            else      split2h(v[2 * j], v[2 * j + 1], Hp[j], Lp[j]);
        } else {
            Hp[j] = packh2(v[2 * j], v[2 * j + 1]);
        }
    }
    ((uint4*)hi)[i] = H;
    if (lo) ((uint4*)lo)[i] = L;
}

// ---------------------------------------------------------------------------
// 2-product fp16 GEMM (batched over z): C = (Ah+Al) @ Wf^T + bias -> fp16.
// CTA 128x128, 4 warps (2x2, warp 64x64), KCH=16, 4-stage pipeline.
// Pipeline order: wait(own fill(c)) -> barrier -> fill(c+3) -> compute(c).
// ---------------------------------------------------------------------------
#define G2ROWB 48
#define G2APL  (128 * G2ROWB)       // 6144 B per plane
#define G2STG  (3 * G2APL)          // Ah, Al, W = 18432 B
#define G2_SMEM (4 * G2STG)         // 73728 B

struct G2Job {
    const uint16_t *Ah, *Al, *Wf;
    const float* bias;
    uint16_t* Of;
    float scale;
};
struct G2Batch { G2Job j[3]; };

__global__ __launch_bounds__(128, 2)
void gemm_2p(G2Batch batch)
{
    extern __shared__ uint32_t smu[];
    const G2Job jb = batch.j[blockIdx.z];
    const int tid = threadIdx.x, warp = tid >> 5, lane = tid & 31;
    const int wm = warp & 1, wn = warp >> 1;
    const int m0 = blockIdx.y * 128, n0 = blockIdx.x * 128;
    const uint32_t smub = smem_u32(smu);
    const uint32_t aoff = (uint32_t)(((lane & 7) + ((lane >> 3) & 1) * 8) * G2ROWB +
                                     ((lane >> 4) << 4));
    const uint32_t boff = (uint32_t)(((lane & 7) + ((lane >> 4) << 3)) * G2ROWB +
                                     (((lane >> 3) & 1) << 4));

    float d[4][8][4];
    #pragma unroll
    for (int mi = 0; mi < 4; mi++)
        #pragma unroll
        for (int ni = 0; ni < 8; ni++)
            #pragma unroll
            for (int x = 0; x < 4; x++) d[mi][ni][x] = 0.f;

    auto fill = [&](int c) {
        const int k0 = c * 16;
        const uint32_t base = smub + (c & 3) * G2STG;
        #pragma unroll
        for (int i = 0; i < 6; i++) {
            const int f = tid + i * 128;          // 0..767
            const int pl = f >> 8;                // 0=Ah 1=Al 2=W
            const int rr = (f & 255) >> 1, sg = f & 1;
            const uint16_t* src = (pl == 0 ? jb.Ah : pl == 1 ? jb.Al : jb.Wf);
            const int rbase = (pl == 2) ? n0 : m0;
            CP16(base + pl * G2APL + rr * G2ROWB + sg * 16,
                 src + (size_t)(rbase + rr) * 1024 + k0 + sg * 8);
        }
        CP_COMMIT();
    };

    fill(0); fill(1); fill(2);

    for (int c = 0; c < 64; c++) {
        asm volatile("cp.async.wait_group 2;" ::: "memory");  // own fill(c) done
        __syncthreads();      // ALL threads' fill(c) visible; reads of c-1 done
        if (c + 3 < 64) fill(c + 3);
        else CP_COMMIT();

        const uint32_t stB = smub + (c & 3) * G2STG;
        const uint32_t aA = stB + (uint32_t)(wm * 64 * G2ROWB) + aoff;
        const uint32_t aB = stB + 2 * G2APL + (uint32_t)(wn * 64 * G2ROWB) + boff;

        uint32_t ah[4][4], bh[4][4];
        #pragma unroll
        for (int p = 0; p < 4; p++) ldsm_x4(bh[p], aB + p * 16 * G2ROWB);
        #pragma unroll
        for (int mi = 0; mi < 4; mi++) ldsm_x4(ah[mi], aA + mi * 16 * G2ROWB);
        #pragma unroll
        for (int mi = 0; mi < 4; mi++)
            #pragma unroll
            for (int p = 0; p < 4; p++) {
                mma_f16(d[mi][2 * p],     ah[mi], &bh[p][0]);
                mma_f16(d[mi][2 * p + 1], ah[mi], &bh[p][2]);
            }
        #pragma unroll
        for (int mi = 0; mi < 4; mi++) ldsm_x4(ah[mi], aA + G2APL + mi * 16 * G2ROWB);
        #pragma unroll
        for (int mi = 0; mi < 4; mi++)
            #pragma unroll
            for (int p = 0; p < 4; p++) {
                mma_f16(d[mi][2 * p],     ah[mi], &bh[p][0]);
                mma_f16(d[mi][2 * p + 1], ah[mi], &bh[p][2]);
            }
    }

    const int row0 = m0 + wm * 64 + (lane >> 2);
    const int colb = n0 + wn * 64 + 2 * (lane & 3);
    #pragma unroll
    for (int ni = 0; ni < 8; ni++) {
        const int cc = colb + ni * 8;
        const float b0 = jb.bias[cc], b1 = jb.bias[cc + 1];
        #pragma unroll
        for (int mi = 0; mi < 4; mi++)
            #pragma unroll
            for (int hf = 0; hf < 2; hf++) {
                const int r = row0 + mi * 16 + 8 * hf;
                const float v0 = (d[mi][ni][2 * hf]     + b0) * jb.scale;
                const float v1 = (d[mi][ni][2 * hf + 1] + b1) * jb.scale;
                ((uint32_t*)jb.Of)[(size_t)r * 512 + cc / 2] = packh2(v0, v1);
            }
    }
}

// ---------------------------------------------------------------------------
// split-bf16 3-product GEMM (output projection): C = CTX @ Wo^T + bias -> fp32
// Same corrected pipeline ordering.
// ---------------------------------------------------------------------------
#define GROWB 48
#define GPLANEB (128 * GROWB)
#define GSTAGEB (4 * GPLANEB)
#define GEMM_SMEM (4 * GSTAGEB)   // 98304

__global__ __launch_bounds__(128, 2)
void gemm_bf16s(const uint16_t* __restrict__ Ah, const uint16_t* __restrict__ Al,
                const uint16_t* __restrict__ Bh, const uint16_t* __restrict__ Bl,
                const float* __restrict__ bias, float* __restrict__ Cf)
{
    extern __shared__ uint32_t smu[];
    const int tid = threadIdx.x, warp = tid >> 5, lane = tid & 31;
    const int wm = warp & 1, wn = warp >> 1;
    const int m0 = blockIdx.y * 128, n0 = blockIdx.x * 128;
    const uint32_t smub = smem_u32(smu);
    const uint32_t aoff = (uint32_t)(((lane & 7) + ((lane >> 3) & 1) * 8) * GROWB +
                                     ((lane >> 4) << 4));
    const uint32_t boff = (uint32_t)(((lane & 7) + ((lane >> 4) << 3)) * GROWB +
                                     (((lane >> 3) & 1) << 4));

    float d[4][8][4];
    #pragma unroll
    for (int mi = 0; mi < 4; mi++)
        #pragma unroll
        for (int ni = 0; ni < 8; ni++)
            #pragma unroll
            for (int x = 0; x < 4; x++) d[mi][ni][x] = 0.f;

    auto fill = [&](int c) {
        const int k0 = c * 16;
        const uint32_t base = smub + (c & 3) * GSTAGEB;
        const size_t ga = (size_t)(m0 + tid) * 1024 + k0;
        const size_t gb = (size_t)(n0 + tid) * 1024 + k0;
        const uint32_t so = (uint32_t)(tid * GROWB);
        #pragma unroll
        for (int sg = 0; sg < 2; sg++) {
            CP16(base + 0 * GPLANEB + so + sg * 16, Ah + ga + sg * 8);
            CP16(base + 1 * GPLANEB + so + sg * 16, Al + ga + sg * 8);
            CP16(base + 2 * GPLANEB + so + sg * 16, Bh + gb + sg * 8);
            CP16(base + 3 * GPLANEB + so + sg * 16, Bl + gb + sg * 8);
        }
        CP_COMMIT();
    };

    fill(0); fill(1); fill(2);

    for (int c = 0; c < 64; c++) {
        asm volatile("cp.async.wait_group 2;" ::: "memory");
        __syncthreads();
        if (c + 3 < 64) fill(c + 3);
        else CP_COMMIT();

        const uint32_t stB = smub + (c & 3) * GSTAGEB;
        const uint32_t aA = stB + (uint32_t)(wm * 64 * GROWB) + aoff;
        const uint32_t aB = stB + 2 * GPLANEB + (uint32_t)(wn * 64 * GROWB) + boff;

        uint32_t ah[4][4], bh[4][4], bl[4][4];
        #pragma unroll
        for (int mi = 0; mi < 4; mi++) ldsm_x4(ah[mi], aA + mi * 16 * GROWB);
        #pragma unroll
        for (int p = 0; p < 4; p++) ldsm_x4(bh[p], aB + p * 16 * GROWB);
        #pragma unroll
        for (int mi = 0; mi < 4; mi++)
            #pragma unroll
            for (int p = 0; p < 4; p++) {
                mma_bf16(d[mi][2 * p],     ah[mi], &bh[p][0]);
                mma_bf16(d[mi][2 * p + 1], ah[mi], &bh[p][2]);
            }
        #pragma unroll
        for (int p = 0; p < 4; p++) ldsm_x4(bl[p], aB + GPLANEB + p * 16 * GROWB);
        #pragma unroll
        for (int mi = 0; mi < 4; mi++)
            #pragma unroll
            for (int p = 0; p < 4; p++) {
                mma_bf16(d[mi][2 * p],     ah[mi], &bl[p][0]);
                mma_bf16(d[mi][2 * p + 1], ah[mi], &bl[p][2]);
            }
        #pragma unroll
        for (int mi = 0; mi < 4; mi++) ldsm_x4(ah[mi], aA + GPLANEB + mi * 16 * GROWB);
        #pragma unroll
        for (int mi = 0; mi < 4; mi++)
            #pragma unroll
            for (int p = 0; p < 4; p++) {
                mma_bf16(d[mi][2 * p],     ah[mi], &bh[p][0]);
                mma_bf16(d[mi][2 * p + 1], ah[mi], &bh[p][2]);
            }
    }

    const int row0 = m0 + wm * 64 + (lane >> 2);
    const int colb = n0 + wn * 64 + 2 * (lane & 3);
    #pragma unroll
    for (int ni = 0; ni < 8; ni++) {
        const int cc = colb + ni * 8;
        const float b0 = bias[cc], b1 = bias[cc + 1];
        #pragma unroll
        for (int mi = 0; mi < 4; mi++)
            #pragma unroll
            for (int hf = 0; hf < 2; hf++) {
                const int r = row0 + mi * 16 + 8 * hf;
                float2 w = {d[mi][ni][2 * hf] + b0, d[mi][ni][2 * hf + 1] + b1};
                *(float2*)(Cf + (size_t)r * 1024 + cc) = w;
            }
    }
}

// ---------------------------------------------------------------------------
// Flash attention (causal), fp16 single-product MMAs (fp32 acc).
// Corrected pipeline ordering: wait -> barrier -> fill -> compute.
// ---------------------------------------------------------------------------
#define KROWB 144
#define KPL   (64 * KROWB)
#define ASTGB (2 * KPL)
#define ATT_SMEM (3 * ASTGB)        // 55296

__global__ __launch_bounds__(128, 2)
void attn_f16(const uint16_t* __restrict__ Qf, const uint16_t* __restrict__ Kf,
              const uint16_t* __restrict__ Vf,
              uint16_t* __restrict__ Ch, uint16_t* __restrict__ Cl)
{
    extern __shared__ uint32_t smu[];
    const int tid = threadIdx.x, lane = tid & 31, warp = tid >> 5;
    const int r = lane >> 2, cth = lane & 3;
    const int qi = gridDim.x - 1 - blockIdx.x;
    const int hd = blockIdx.y, b = blockIdx.z;
    const int q0r = qi * 64;
    const uint32_t smub = smem_u32(smu);
    const size_t hoff = (size_t)hd * 64;

    const uint32_t koff  = (uint32_t)(((lane & 7) + ((lane >> 4) << 3)) * KROWB +
                                      (((lane >> 3) & 1) << 4));
    const uint32_t aoffq = (uint32_t)(((lane & 7) + ((lane >> 3) & 1) * 8) * KROWB +
                                      ((lane >> 4) << 4));
    const uint32_t voff  = (uint32_t)((lane & 15) * KROWB + ((lane >> 4) << 4));

    #pragma unroll
    for (int i = 0; i < 4; i++) {
        const int f = tid + i * 128;
        const int rr = f >> 3, sg = f & 7;
        CP16(smub + 2 * ASTGB + rr * KROWB + sg * 16,
             Qf + (size_t)(b * Ll + q0r + rr) * 1024 + hoff + sg * 8);
    }
    CP_COMMIT();

    auto fillKV = [&](int kt) {
        const int k0 = kt * 64;
        const uint32_t dstB = smub + (kt % 3) * ASTGB;
        #pragma unroll
        for (int i = 0; i < 8; i++) {
            const int f = tid + i * 128;
            const int pl = f >> 9, rr = (f & 511) >> 3, sg = f & 7;
            const uint16_t* src = pl ? Vf : Kf;
            CP16(dstB + pl * KPL + rr * KROWB + sg * 16,
                 src + (size_t)(b * Ll + k0 + rr) * 1024 + hoff + sg * 8);
        }
        CP_COMMIT();
    };

    fillKV(0);
    asm volatile("cp.async.wait_group 1;" ::: "memory");   // own Q copies done
    __syncthreads();                                       // ALL Q copies visible

    uint32_t qf[4][4];
    {
        const uint32_t qb = smub + 2 * ASTGB + (uint32_t)(warp * 16 * KROWB) + aoffq;
        #pragma unroll
        for (int j = 0; j < 4; j++) ldsm_x4(qf[j], qb + j * 32);
    }
    __syncthreads();   // all Q reads done (stage-2 area reusable)

    const int ktmax = qi + 1;
    if (ktmax > 1) fillKV(1);
    else CP_COMMIT();

    float m_i[2] = {-1e30f, -1e30f}, l_i[2] = {0.f, 0.f};
    float o[8][4];
    #pragma unroll
    for (int ni = 0; ni < 8; ni++)
        #pragma unroll
        for (int x = 0; x < 4; x++) o[ni][x] = 0.f;

    for (int kt = 0; kt < ktmax; kt++) {
        asm volatile("cp.async.wait_group 1;" ::: "memory");  // own fillKV(kt) done
        __syncthreads();      // ALL fillKV(kt) visible; reads of kt-1 done
        if (kt + 2 < ktmax) fillKV(kt + 2);
        else CP_COMMIT();

        const uint32_t stB = smub + (kt % 3) * ASTGB;

        float sacc[8][4];
        #pragma unroll
        for (int ni = 0; ni < 8; ni++)
            #pragma unroll
            for (int x = 0; x < 4; x++) sacc[ni][x] = 0.f;

        #pragma unroll
        for (int j = 0; j < 4; j++) {
            #pragma unroll
            for (int nip = 0; nip < 4; nip++) {
                const uint32_t ka = stB + nip * (16 * KROWB) + koff + j * 32;
                uint32_t bf[4];
                ldsm_x4(bf, ka);
                mma_f16(sacc[2 * nip],     qf[j], &bf[0]);
                mma_f16(sacc[2 * nip + 1], qf[j], &bf[2]);
            }
        }

        const int k0 = kt * 64;
        if (kt == ktmax - 1) {
            const int rowb = q0r + warp * 16 + r;
            #pragma unroll
            for (int ni = 0; ni < 8; ni++) {
                const int colb = k0 + ni * 8 + 2 * cth;
                #pragma unroll
                for (int x = 0; x < 4; x++)
                    if (colb + (x & 1) > rowb + 8 * (x >> 1)) sacc[ni][x] = -1e30f;
            }
        }

        uint32_t pp[8][2];
        #pragma unroll
        for (int h = 0; h < 2; h++) {
            float mx = -1e30f;
            #pragma unroll
            for (int ni = 0; ni < 8; ni++)
                mx = fmaxf(mx, fmaxf(sacc[ni][2 * h], sacc[ni][2 * h + 1]));
            mx = fmaxf(mx, __shfl_xor_sync(0xffffffffu, mx, 1));
            mx = fmaxf(mx, __shfl_xor_sync(0xffffffffu, mx, 2));
            const float mnew = fmaxf(m_i[h], mx);
            const float alpha = __expf(m_i[h] - mnew);
            float sum = 0.f;
            #pragma unroll
            for (int ni = 0; ni < 8; ni++) {
                const float p0 = __expf(sacc[ni][2 * h] - mnew);
                const float p1 = __expf(sacc[ni][2 * h + 1] - mnew);
                sum += p0 + p1;
                pp[ni][h] = packh2(p0, p1);
                o[ni][2 * h]     *= alpha;
                o[ni][2 * h + 1] *= alpha;
            }
            sum += __shfl_xor_sync(0xffffffffu, sum, 1);
            sum += __shfl_xor_sync(0xffffffffu, sum, 2);
            l_i[h] = l_i[h] * alpha + sum;
            m_i[h] = mnew;
        }

        const uint32_t vB = stB + KPL;
        #pragma unroll
        for (int kk = 0; kk < 4; kk++) {
            uint32_t ahp[4];
            ahp[0] = pp[2 * kk][0];
            ahp[1] = pp[2 * kk][1];
            ahp[2] = pp[2 * kk + 1][0];
            ahp[3] = pp[2 * kk + 1][1];
            #pragma unroll
            for (int nip = 0; nip < 4; nip++) {
                const uint32_t va = vB + kk * (16 * KROWB) + nip * 32 + voff;
                uint32_t vf4[4];
                ldsm_x4_t(vf4, va);
                mma_f16(o[2 * nip],     ahp, &vf4[0]);
                mma_f16(o[2 * nip + 1], ahp, &vf4[2]);
            }
        }
    }

    #pragma unroll
    for (int h = 0; h < 2; h++) {
        const float inv = 1.0f / l_i[h];
        const int row = q0r + warp * 16 + r + 8 * h;
        const size_t base = ((size_t)(b * Ll + row)) * 512 + hd * 32;
        #pragma unroll
        for (int ni = 0; ni < 8; ni++) {
            uint32_t hv, lv;
            split2(o[ni][2 * h] * inv, o[ni][2 * h + 1] * inv, hv, lv);
            ((uint32_t*)Ch)[base + ni * 4 + cth] = hv;
            ((uint32_t*)Cl)[base + ni * 4 + cth] = lv;
        }
    }
}

// ---------------------------------------------------------------------------
extern "C" void kernel_launch(void* const* d_in, const int* in_sizes, int n_in,
                              void* d_out, int out_size)
{
    const float* q    = (const float*)d_in[0];
    const float* k    = (const float*)d_in[1];
    const float* v    = (const float*)d_in[2];
    const float* wq_w = (const float*)d_in[3];
    const float* wq_b = (const float*)d_in[4];
    const float* wk_w = (const float*)d_in[5];
    const float* wk_b = (const float*)d_in[6];
    const float* wv_w = (const float*)d_in[7];
    const float* wv_b = (const float*)d_in[8];
    const float* wo_w = (const float*)d_in[9];
    const float* wo_b = (const float*)d_in[10];
    float* out = (float*)d_out;

    uint16_t* P;
    cudaGetSymbolAddress((void**)&P, g_buf);
    uint16_t* W = P + 11 * NPLANE;
    #define PLN(i) (P + (size_t)(i) * NPLANE)
    #define WPL(i) (W + (size_t)(i) * WPLANE)

    cudaFuncSetAttribute(gemm_2p, cudaFuncAttributeMaxDynamicSharedMemorySize,
                         G2_SMEM);
    cudaFuncSetAttribute(gemm_bf16s, cudaFuncAttributeMaxDynamicSharedMemorySize,
                         GEMM_SMEM);
    cudaFuncSetAttribute(attn_f16, cudaFuncAttributeMaxDynamicSharedMemorySize,
                         ATT_SMEM);

    const int n8a = (int)(NPLANE / 8), n8w = (int)(WPLANE / 8);

    // activations -> fp16 hi/lo
    Split4 sa;
    sa.in[0] = q; sa.hi[0] = PLN(0); sa.lo[0] = PLN(1); sa.bf16[0] = 0;
    sa.in[1] = k; sa.hi[1] = PLN(2); sa.lo[1] = PLN(3); sa.bf16[1] = 0;
    sa.in[2] = v; sa.hi[2] = PLN(4); sa.lo[2] = PLN(5); sa.bf16[2] = 0;
    sa.in[3] = q; sa.hi[3] = PLN(0); sa.lo[3] = PLN(1); sa.bf16[3] = 0;  // unused
    split_multi<<<dim3(n8a / 256, 3), 256>>>(sa, n8a);

    // weights: wq/wk/wv -> single fp16; wo -> bf16 hi/lo
    Split4 sw;
    sw.in[0] = wq_w; sw.hi[0] = WPL(0); sw.lo[0] = nullptr; sw.bf16[0] = 0;
    sw.in[1] = wk_w; sw.hi[1] = WPL(1); sw.lo[1] = nullptr; sw.bf16[1] = 0;
    sw.in[2] = wv_w; sw.hi[2] = WPL(2); sw.lo[2] = nullptr; sw.bf16[2] = 0;
    sw.in[3] = wo_w; sw.hi[3] = WPL(3); sw.lo[3] = WPL(4);  sw.bf16[3] = 1;
    split_multi<<<dim3(n8w / 256, 4), 256>>>(sw, n8w);

    // fused Q/K/V projections, 2-product fp16 (Q pre-scaled by 1/8)
    G2Batch proj;
    proj.j[0] = {PLN(0), PLN(1), WPL(0), wq_b, PLN(6), 0.125f};
    proj.j[1] = {PLN(2), PLN(3), WPL(1), wk_b, PLN(7), 1.0f};
    proj.j[2] = {PLN(4), PLN(5), WPL(2), wv_b, PLN(8), 1.0f};
    dim3 gg(1024 / 128, MTOT / 128, 3);   // (8, 64, 3)
    gemm_2p<<<gg, 128, G2_SMEM>>>(proj);

    dim3 ga(Ll / 64, Hh, Bb);             // (32, 16, 4)
    attn_f16<<<ga, 128, ATT_SMEM>>>(PLN(6), PLN(7), PLN(8), PLN(9), PLN(10));

    // output projection (bf16 3-product, proven) -> fp32
    dim3 go(1024 / 128, MTOT / 128);      // (8, 64)
    gemm_bf16s<<<go, 128, GEMM_SMEM>>>(PLN(9), PLN(10), WPL(3), WPL(4), wo_b, out);
    #undef PLN
    #undef WPL
}

// round 17
// speedup vs baseline: 4.0227x; 1.1395x over previous
#include <cuda_runtime.h>
#include <cuda_fp16.h>
#include <math.h>
#include <stdint.h>

#define Dm   1024
#define Hh   16
#define Bb   4
#define Ll   2048
#define MTOT (Bb * Ll)
#define NPLANE ((size_t)MTOT * Dm)   // 8388608
#define WPLANE ((size_t)Dm * Dm)

// planes 0-5: act fp16 hi/lo (q,k,v); 6-8: Qf,Kf,Vf fp16; 9-10: ctx fp16 hi/lo
// weights: wq,wk,wv,wo single fp16 (WPL 0-3)
__device__ __align__(16) uint16_t g_buf[11 * NPLANE + 4 * WPLANE];

__device__ __forceinline__ uint32_t smem_u32(const void* p) {
    uint32_t a;
    asm("{ .reg .u64 t; cvta.to.shared.u64 t, %1; cvt.u32.u64 %0, t; }"
        : "=r"(a) : "l"(p));
    return a;
}

// fp16 split (hi/lo, unscaled lo; exact to ~2^-22)
__device__ __forceinline__ void split2h(float x0, float x1,
                                        uint32_t& hi, uint32_t& lo) {
    __half2 hh = __floats2half2_rn(x0, x1);
    float2 fb = __half22float2(hh);
    __half2 ll = __floats2half2_rn(x0 - fb.x, x1 - fb.y);
    hi = *(uint32_t*)&hh;
    lo = *(uint32_t*)&ll;
}
__device__ __forceinline__ uint32_t packh2(float x0, float x1) {
    __half2 h = __floats2half2_rn(x0, x1);
    return *(uint32_t*)&h;
}

__device__ __forceinline__ void mma_f16(float d[4], const uint32_t a[4],
                                        const uint32_t b[2]) {
    asm volatile(
        "mma.sync.aligned.m16n8k16.row.col.f32.f16.f16.f32 "
        "{%0,%1,%2,%3}, {%4,%5,%6,%7}, {%8,%9}, {%0,%1,%2,%3};"
        : "+f"(d[0]), "+f"(d[1]), "+f"(d[2]), "+f"(d[3])
        : "r"(a[0]), "r"(a[1]), "r"(a[2]), "r"(a[3]), "r"(b[0]), "r"(b[1]));
}
__device__ __forceinline__ void ldsm_x4(uint32_t r[4], uint32_t a) {
    asm volatile("ldmatrix.sync.aligned.m8n8.x4.shared.b16 {%0,%1,%2,%3}, [%4];"
                 : "=r"(r[0]), "=r"(r[1]), "=r"(r[2]), "=r"(r[3]) : "r"(a));
}
__device__ __forceinline__ void ldsm_x4_t(uint32_t r[4], uint32_t a) {
    asm volatile("ldmatrix.sync.aligned.m8n8.x4.trans.shared.b16 {%0,%1,%2,%3}, [%4];"
                 : "=r"(r[0]), "=r"(r[1]), "=r"(r[2]), "=r"(r[3]) : "r"(a));
}
#define CP16(smaddr, gptr) \
    asm volatile("cp.async.cg.shared.global [%0], [%1], 16;" \
                 :: "r"(smaddr), "l"(gptr))
#define CP_COMMIT() asm volatile("cp.async.commit_group;")

// ---------------------------------------------------------------------------
// Split kernels. lo != null -> fp16 hi/lo split; lo == null -> single fp16.
// ---------------------------------------------------------------------------
struct Split4 {
    const float* in[4];
    uint16_t* hi[4];
    uint16_t* lo[4];
};
__global__ __launch_bounds__(256)
void split_multi(Split4 a, int n8)
{
    const int z = blockIdx.y;
    const float* in = a.in[z];
    uint16_t* hi = a.hi[z];
    uint16_t* lo = a.lo[z];
    const int i = blockIdx.x * 256 + threadIdx.x;
    if (i >= n8) return;
    const float4* in4 = (const float4*)in;
    float4 x = in4[2 * i], y = in4[2 * i + 1];
    float v[8] = {x.x, x.y, x.z, x.w, y.x, y.y, y.z, y.w};
    uint4 H, L;
    uint32_t* Hp = &H.x;
    uint32_t* Lp = &L.x;
    #pragma unroll
    for (int j = 0; j < 4; j++) {
        if (lo) split2h(v[2 * j], v[2 * j + 1], Hp[j], Lp[j]);
        else    Hp[j] = packh2(v[2 * j], v[2 * j + 1]);
    }
    ((uint4*)hi)[i] = H;
    if (lo) ((uint4*)lo)[i] = L;
}

// ---------------------------------------------------------------------------
// 2-product fp16 GEMM (batched over z): C = (Ah+Al) @ Wf^T + bias.
// Output: fp16 plane (Of) or fp32 (Cf). CTA 128x128, 4 warps, KCH=16,
// 4-stage pipeline with race-safe ordering (wait -> barrier -> fill).
// ---------------------------------------------------------------------------
#define G2ROWB 48
#define G2APL  (128 * G2ROWB)
#define G2STG  (3 * G2APL)          // 18432 B
#define G2_SMEM (4 * G2STG)         // 73728 B

struct G2Job {
    const uint16_t *Ah, *Al, *Wf;
    const float* bias;
    uint16_t* Of;       // fp16 out (if Cf null)
    float* Cf;          // fp32 out
    float scale;
};
struct G2Batch { G2Job j[3]; };

__global__ __launch_bounds__(128, 2)
void gemm_2p(G2Batch batch)
{
    extern __shared__ uint32_t smu[];
    const G2Job jb = batch.j[blockIdx.z];
    const int tid = threadIdx.x, warp = tid >> 5, lane = tid & 31;
    const int wm = warp & 1, wn = warp >> 1;
    const int m0 = blockIdx.y * 128, n0 = blockIdx.x * 128;
    const uint32_t smub = smem_u32(smu);
    const uint32_t aoff = (uint32_t)(((lane & 7) + ((lane >> 3) & 1) * 8) * G2ROWB +
                                     ((lane >> 4) << 4));
    const uint32_t boff = (uint32_t)(((lane & 7) + ((lane >> 4) << 3)) * G2ROWB +
                                     (((lane >> 3) & 1) << 4));

    float d[4][8][4];
    #pragma unroll
    for (int mi = 0; mi < 4; mi++)
        #pragma unroll
        for (int ni = 0; ni < 8; ni++)
            #pragma unroll
            for (int x = 0; x < 4; x++) d[mi][ni][x] = 0.f;

    auto fill = [&](int c) {
        const int k0 = c * 16;
        const uint32_t base = smub + (c & 3) * G2STG;
        #pragma unroll
        for (int i = 0; i < 6; i++) {
            const int f = tid + i * 128;          // 0..767
            const int pl = f >> 8;                // 0=Ah 1=Al 2=W
            const int rr = (f & 255) >> 1, sg = f & 1;
            const uint16_t* src = (pl == 0 ? jb.Ah : pl == 1 ? jb.Al : jb.Wf);
            const int rbase = (pl == 2) ? n0 : m0;
            CP16(base + pl * G2APL + rr * G2ROWB + sg * 16,
                 src + (size_t)(rbase + rr) * 1024 + k0 + sg * 8);
        }
        CP_COMMIT();
    };

    fill(0); fill(1); fill(2);

    for (int c = 0; c < 64; c++) {
        asm volatile("cp.async.wait_group 2;" ::: "memory");
        __syncthreads();
        if (c + 3 < 64) fill(c + 3);
        else CP_COMMIT();

        const uint32_t stB = smub + (c & 3) * G2STG;
        const uint32_t aA = stB + (uint32_t)(wm * 64 * G2ROWB) + aoff;
        const uint32_t aB = stB + 2 * G2APL + (uint32_t)(wn * 64 * G2ROWB) + boff;

        uint32_t ah[4][4], bh[4][4];
        #pragma unroll
        for (int p = 0; p < 4; p++) ldsm_x4(bh[p], aB + p * 16 * G2ROWB);
        #pragma unroll
        for (int mi = 0; mi < 4; mi++) ldsm_x4(ah[mi], aA + mi * 16 * G2ROWB);
        #pragma unroll
        for (int mi = 0; mi < 4; mi++)
            #pragma unroll
            for (int p = 0; p < 4; p++) {
                mma_f16(d[mi][2 * p],     ah[mi], &bh[p][0]);
                mma_f16(d[mi][2 * p + 1], ah[mi], &bh[p][2]);
            }
        #pragma unroll
        for (int mi = 0; mi < 4; mi++) ldsm_x4(ah[mi], aA + G2APL + mi * 16 * G2ROWB);
        #pragma unroll
        for (int mi = 0; mi < 4; mi++)
            #pragma unroll
            for (int p = 0; p < 4; p++) {
                mma_f16(d[mi][2 * p],     ah[mi], &bh[p][0]);
                mma_f16(d[mi][2 * p + 1], ah[mi], &bh[p][2]);
            }
    }

    const int row0 = m0 + wm * 64 + (lane >> 2);
    const int colb = n0 + wn * 64 + 2 * (lane & 3);
    #pragma unroll
    for (int ni = 0; ni < 8; ni++) {
        const int cc = colb + ni * 8;
        const float b0 = jb.bias[cc], b1 = jb.bias[cc + 1];
        #pragma unroll
        for (int mi = 0; mi < 4; mi++)
            #pragma unroll
            for (int hf = 0; hf < 2; hf++) {
                const int r = row0 + mi * 16 + 8 * hf;
                const float v0 = d[mi][ni][2 * hf]     + b0;
                const float v1 = d[mi][ni][2 * hf + 1] + b1;
                if (jb.Cf) {
                    float2 w = {v0, v1};
                    *(float2*)(jb.Cf + (size_t)r * 1024 + cc) = w;
                } else {
                    ((uint32_t*)jb.Of)[(size_t)r * 512 + cc / 2] =
                        packh2(v0 * jb.scale, v1 * jb.scale);
                }
            }
    }
}

// ---------------------------------------------------------------------------
// Flash attention (causal), fp16 single-product MMAs (fp32 acc).
// Block = (b, h, 128-row q tile); 128 thr / 4 warps, each warp owns TWO m16
// row-groups (32 q-rows) -> every K/V ldsm feeds 4 MMAs. 3-stage KV pipeline.
// ---------------------------------------------------------------------------
#define KROWB 144
#define KPL   (64 * KROWB)          // 9216
#define ASTGB (2 * KPL)             // 18432
#define ATT_SMEM (3 * ASTGB)        // 55296

__global__ __launch_bounds__(128, 2)
void attn_f16(const uint16_t* __restrict__ Qf, const uint16_t* __restrict__ Kf,
              const uint16_t* __restrict__ Vf,
              uint16_t* __restrict__ Ch, uint16_t* __restrict__ Cl)
{
    extern __shared__ uint32_t smu[];
    const int tid = threadIdx.x, lane = tid & 31, warp = tid >> 5;
    const int r = lane >> 2, cth = lane & 3;
    const int qi = gridDim.x - 1 - blockIdx.x;   // heavy tiles first
    const int hd = blockIdx.y, b = blockIdx.z;
    const int q0 = qi * 128;
    const uint32_t smub = smem_u32(smu);
    const size_t hoff = (size_t)hd * 64;

    const uint32_t koff  = (uint32_t)(((lane & 7) + ((lane >> 4) << 3)) * KROWB +
                                      (((lane >> 3) & 1) << 4));
    const uint32_t aoffq = (uint32_t)(((lane & 7) + ((lane >> 3) & 1) * 8) * KROWB +
                                      ((lane >> 4) << 4));
    const uint32_t voff  = (uint32_t)((lane & 15) * KROWB + ((lane >> 4) << 4));

    // Q plane (128 rows x 128 B) -> stage-2 area (group 0)
    #pragma unroll
    for (int i = 0; i < 8; i++) {
        const int f = tid + i * 128;       // 0..1023
        const int rr = f >> 3, sg = f & 7;
        CP16(smub + 2 * ASTGB + rr * KROWB + sg * 16,
             Qf + (size_t)(b * Ll + q0 + rr) * 1024 + hoff + sg * 8);
    }
    CP_COMMIT();

    auto fillKV = [&](int kt) {
        const int k0 = kt * 64;
        const uint32_t dstB = smub + (kt % 3) * ASTGB;
        #pragma unroll
        for (int i = 0; i < 8; i++) {
            const int f = tid + i * 128;
            const int pl = f >> 9, rr = (f & 511) >> 3, sg = f & 7;
            const uint16_t* src = pl ? Vf : Kf;
            CP16(dstB + pl * KPL + rr * KROWB + sg * 16,
                 src + (size_t)(b * Ll + k0 + rr) * 1024 + hoff + sg * 8);
        }
        CP_COMMIT();
    };

    fillKV(0);
    asm volatile("cp.async.wait_group 1;" ::: "memory");   // own Q copies done
    __syncthreads();                                       // ALL Q copies visible

    uint32_t qf[2][4][4];
    #pragma unroll
    for (int g = 0; g < 2; g++) {
        const uint32_t qb = smub + 2 * ASTGB +
                            (uint32_t)((warp * 32 + g * 16) * KROWB) + aoffq;
        #pragma unroll
        for (int j = 0; j < 4; j++) ldsm_x4(qf[g][j], qb + j * 32);
    }
    __syncthreads();   // Q reads done (stage-2 reusable)

    const int ktmax = 2 * qi + 2;
    if (ktmax > 1) fillKV(1);
    else CP_COMMIT();

    float m_i[2][2], l_i[2][2];
    #pragma unroll
    for (int g = 0; g < 2; g++)
        #pragma unroll
        for (int h = 0; h < 2; h++) { m_i[g][h] = -1e30f; l_i[g][h] = 0.f; }
    float o[2][8][4];
    #pragma unroll
    for (int g = 0; g < 2; g++)
        #pragma unroll
        for (int ni = 0; ni < 8; ni++)
            #pragma unroll
            for (int x = 0; x < 4; x++) o[g][ni][x] = 0.f;

    for (int kt = 0; kt < ktmax; kt++) {
        asm volatile("cp.async.wait_group 1;" ::: "memory");  // own fillKV(kt)
        __syncthreads();      // ALL fillKV(kt) visible; reads of kt-1 done
        if (kt + 2 < ktmax) fillKV(kt + 2);
        else CP_COMMIT();

        const uint32_t stB = smub + (kt % 3) * ASTGB;

        // S = (Q/8) K^T — K ldsm shared by both row groups
        float sacc[2][8][4];
        #pragma unroll
        for (int g = 0; g < 2; g++)
            #pragma unroll
            for (int ni = 0; ni < 8; ni++)
                #pragma unroll
                for (int x = 0; x < 4; x++) sacc[g][ni][x] = 0.f;

        #pragma unroll
        for (int j = 0; j < 4; j++) {
            #pragma unroll
            for (int nip = 0; nip < 4; nip++) {
                const uint32_t ka = stB + nip * (16 * KROWB) + koff + j * 32;
                uint32_t bf[4];
                ldsm_x4(bf, ka);
                #pragma unroll
                for (int g = 0; g < 2; g++) {
                    mma_f16(sacc[g][2 * nip],     qf[g][j], &bf[0]);
                    mma_f16(sacc[g][2 * nip + 1], qf[g][j], &bf[2]);
                }
            }
        }

        const int k0 = kt * 64;
        if (kt >= ktmax - 2) {    // only last two tiles touch the diagonal
            #pragma unroll
            for (int g = 0; g < 2; g++) {
                const int rowb = q0 + warp * 32 + g * 16 + r;
                #pragma unroll
                for (int ni = 0; ni < 8; ni++) {
                    const int colb = k0 + ni * 8 + 2 * cth;
                    #pragma unroll
                    for (int x = 0; x < 4; x++)
                        if (colb + (x & 1) > rowb + 8 * (x >> 1))
                            sacc[g][ni][x] = -1e30f;
                }
            }
        }

        // online softmax per row group
        uint32_t pp[2][8][2];
        #pragma unroll
        for (int g = 0; g < 2; g++)
            #pragma unroll
            for (int h = 0; h < 2; h++) {
                float mx = -1e30f;
                #pragma unroll
                for (int ni = 0; ni < 8; ni++)
                    mx = fmaxf(mx, fmaxf(sacc[g][ni][2 * h], sacc[g][ni][2 * h + 1]));
                mx = fmaxf(mx, __shfl_xor_sync(0xffffffffu, mx, 1));
                mx = fmaxf(mx, __shfl_xor_sync(0xffffffffu, mx, 2));
                const float mnew = fmaxf(m_i[g][h], mx);
                const float alpha = __expf(m_i[g][h] - mnew);
                float sum = 0.f;
                #pragma unroll
                for (int ni = 0; ni < 8; ni++) {
                    const float p0 = __expf(sacc[g][ni][2 * h] - mnew);
                    const float p1 = __expf(sacc[g][ni][2 * h + 1] - mnew);
                    sum += p0 + p1;
                    pp[g][ni][h] = packh2(p0, p1);
                    o[g][ni][2 * h]     *= alpha;
                    o[g][ni][2 * h + 1] *= alpha;
                }
                sum += __shfl_xor_sync(0xffffffffu, sum, 1);
                sum += __shfl_xor_sync(0xffffffffu, sum, 2);
                l_i[g][h] = l_i[g][h] * alpha + sum;
                m_i[g][h] = mnew;
            }

        // O += P V — V ldsm shared by both row groups
        const uint32_t vB = stB + KPL;
        #pragma unroll
        for (int kk = 0; kk < 4; kk++) {
            uint32_t ahp[2][4];
            #pragma unroll
            for (int g = 0; g < 2; g++) {
                ahp[g][0] = pp[g][2 * kk][0];
                ahp[g][1] = pp[g][2 * kk][1];
                ahp[g][2] = pp[g][2 * kk + 1][0];
                ahp[g][3] = pp[g][2 * kk + 1][1];
            }
            #pragma unroll
            for (int nip = 0; nip < 4; nip++) {
                const uint32_t va = vB + kk * (16 * KROWB) + nip * 32 + voff;
                uint32_t vf4[4];
                ldsm_x4_t(vf4, va);
                #pragma unroll
                for (int g = 0; g < 2; g++) {
                    mma_f16(o[g][2 * nip],     ahp[g], &vf4[0]);
                    mma_f16(o[g][2 * nip + 1], ahp[g], &vf4[2]);
                }
            }
        }
    }

    // normalize + fp16-split + write context planes
    #pragma unroll
    for (int g = 0; g < 2; g++)
        #pragma unroll
        for (int h = 0; h < 2; h++) {
            const float inv = 1.0f / l_i[g][h];
            const int row = q0 + warp * 32 + g * 16 + r + 8 * h;
            const size_t base = ((size_t)(b * Ll + row)) * 512 + hd * 32;
            #pragma unroll
            for (int ni = 0; ni < 8; ni++) {
                uint32_t hv, lv;
                split2h(o[g][ni][2 * h] * inv, o[g][ni][2 * h + 1] * inv, hv, lv);
                ((uint32_t*)Ch)[base + ni * 4 + cth] = hv;
                ((uint32_t*)Cl)[base + ni * 4 + cth] = lv;
            }
        }
}

// ---------------------------------------------------------------------------
extern "C" void kernel_launch(void* const* d_in, const int* in_sizes, int n_in,
                              void* d_out, int out_size)
{
    const float* q    = (const float*)d_in[0];
    const float* k    = (const float*)d_in[1];
    const float* v    = (const float*)d_in[2];
    const float* wq_w = (const float*)d_in[3];
    const float* wq_b = (const float*)d_in[4];
    const float* wk_w = (const float*)d_in[5];
    const float* wk_b = (const float*)d_in[6];
    const float* wv_w = (const float*)d_in[7];
    const float* wv_b = (const float*)d_in[8];
    const float* wo_w = (const float*)d_in[9];
    const float* wo_b = (const float*)d_in[10];
    float* out = (float*)d_out;

    uint16_t* P;
    cudaGetSymbolAddress((void**)&P, g_buf);
    uint16_t* W = P + 11 * NPLANE;
    #define PLN(i) (P + (size_t)(i) * NPLANE)
    #define WPL(i) (W + (size_t)(i) * WPLANE)

    cudaFuncSetAttribute(gemm_2p, cudaFuncAttributeMaxDynamicSharedMemorySize,
                         G2_SMEM);
    cudaFuncSetAttribute(attn_f16, cudaFuncAttributeMaxDynamicSharedMemorySize,
                         ATT_SMEM);

    const int n8a = (int)(NPLANE / 8), n8w = (int)(WPLANE / 8);

    // activations -> fp16 hi/lo
    Split4 sa;
    sa.in[0] = q; sa.hi[0] = PLN(0); sa.lo[0] = PLN(1);
    sa.in[1] = k; sa.hi[1] = PLN(2); sa.lo[1] = PLN(3);
    sa.in[2] = v; sa.hi[2] = PLN(4); sa.lo[2] = PLN(5);
    sa.in[3] = q; sa.hi[3] = PLN(0); sa.lo[3] = PLN(1);  // unused
    split_multi<<<dim3(n8a / 256, 3), 256>>>(sa, n8a);

    // weights -> single fp16 planes
    Split4 sw;
    sw.in[0] = wq_w; sw.hi[0] = WPL(0); sw.lo[0] = nullptr;
    sw.in[1] = wk_w; sw.hi[1] = WPL(1); sw.lo[1] = nullptr;
    sw.in[2] = wv_w; sw.hi[2] = WPL(2); sw.lo[2] = nullptr;
    sw.in[3] = wo_w; sw.hi[3] = WPL(3); sw.lo[3] = nullptr;
    split_multi<<<dim3(n8w / 256, 4), 256>>>(sw, n8w);

    // fused Q/K/V projections, 2-product fp16 (Q pre-scaled by 1/8)
    G2Batch proj;
    proj.j[0] = {PLN(0), PLN(1), WPL(0), wq_b, PLN(6), nullptr, 0.125f};
    proj.j[1] = {PLN(2), PLN(3), WPL(1), wk_b, PLN(7), nullptr, 1.0f};
    proj.j[2] = {PLN(4), PLN(5), WPL(2), wv_b, PLN(8), nullptr, 1.0f};
    dim3 gg(1024 / 128, MTOT / 128, 3);   // (8, 64, 3)
    gemm_2p<<<gg, 128, G2_SMEM>>>(proj);

    dim3 ga(Ll / 128, Hh, Bb);            // (16, 16, 4)
    attn_f16<<<ga, 128, ATT_SMEM>>>(PLN(6), PLN(7), PLN(8), PLN(9), PLN(10));

    // output projection, 2-product fp16 (ctx fp16 hi/lo exact) -> fp32
    G2Batch outp;
    outp.j[0] = {PLN(9), PLN(10), WPL(3), wo_b, nullptr, out, 1.0f};
    outp.j[1] = outp.j[0];
    outp.j[2] = outp.j[0];
    dim3 go(1024 / 128, MTOT / 128, 1);   // (8, 64, 1)
    gemm_2p<<<go, 128, G2_SMEM>>>(outp);
    #undef PLN
    #undef WPL
}